// round 10
// baseline (speedup 1.0000x reference)
#include <cuda_runtime.h>
#include <cuda_fp16.h>
#include <math.h>

// ---------------------------------------------------------------------------
// Problem constants
// ---------------------------------------------------------------------------
#define D_MODEL 1024
#define NHEAD   8
#define HDIM    128
#define NQ      256
#define BATCH   8
#define SEQ_S   4096
#define FF_DIM  4096
#define M_TOK   (NQ*BATCH)       // 2048
#define M_MEM   (SEQ_S*BATCH)    // 32768

// ---------------------------------------------------------------------------
// Scratch (offsets in floats)
// ---------------------------------------------------------------------------
#define OFF_X      0LL            // half [2048*1024]
#define OFF_QKV    (OFF_X    + 2097152LL)   // fp32 [2048,3072]
#define OFF_PACK   (OFF_QKV  + 6291456LL)   // half q,k,v packed
#define OFF_SCORES (OFF_PACK + 6291456LL)   // fp32 scores
#define OFF_O      (OFF_SCORES + 8388608LL) // fp32 self-attn o
#define OFF_OREP   (OFF_O    + 2097152LL)   // half
#define OFF_Q1     (OFF_OREP + 2097152LL)   // fp32
#define OFF_QC     (OFF_Q1   + 2097152LL)   // half cross Q
#define OFF_K      (OFF_QC   + 2097152LL)   // half K' [8,4096,1024]
#define OFF_V      (OFF_K    + 33554432LL)  // half V'
#define OFF_Q2     (OFF_V    + 33554432LL)  // fp32
#define OFF_H      (OFF_Q2   + 2097152LL)   // half FFN hidden
#define OFF_QM     (OFF_H    + 8388608LL)   // half
#define OFF_SCH    (OFF_QM   + 2097152LL)   // half softmax out (8.4M halves)
#define OFF_GOH    (OFF_SCH  + 4194304LL)   // half cross attn_out
#define OFF_WH     (OFF_GOH  + 1048576LL)   // half weights (20971520 halves)
#define OFF_MEMH   (OFF_WH   + 10485760LL)  // half memory (33554432 halves)
#define SCRATCH_TOTAL (OFF_MEMH + 16777216LL)

__device__ float g_scratch[SCRATCH_TOTAL];

// half-weight sub-offsets (in halves, within WH region)
#define H_SAIN   0LL
#define H_SAOUT  3145728LL
#define H_Q      4194304LL
#define H_K      5242880LL
#define H_V      6291456LL
#define H_O      7340032LL
#define H_1      8388608LL
#define H_2      12582912LL
#define H_MASK   16777216LL

// ---------------------------------------------------------------------------
// Helpers
// ---------------------------------------------------------------------------
__device__ __forceinline__ float gelu_exact(float x) {
    return 0.5f * x * (1.0f + erff(x * 0.70710678118654752f));
}

// ---------------------------------------------------------------------------
// fp16 tensor-core batched GEMM (m16n8k16, fp32 accum), 4-stage cp.async.
// 128 threads, 4 warps, warp tile 64x64, CTA tile 128x128, kc=32 per stage.
//   C = act( alpha * A @ op(B) + bias + resid )
//   A half row-major [M,K]. BLAYOUT 0: B half [N,K] (A@B^T). 1: B half [K,N].
//   OUTH: write __half output (no resid in that mode). permP/permQ row remap.
// smem halves: As [4][128][40], Bs [4] (layout0 [128][40] / layout1 [32][136])
// Dynamic smem: 4 * 5120 halves * 2 arrays * 2B = 81920 B.
// K must be a multiple of 32 (all calls: 128,256,1024,4096).
// ---------------------------------------------------------------------------
#define GSTAGES 4
#define GSMEM_BYTES (GSTAGES * 5120 * 2 * 2)

template<int BLAYOUT, int ACT, int OUTH>
__global__ void __launch_bounds__(128, 2)
gemm_tc(const __half* __restrict__ A, const __half* __restrict__ B,
        const float* __restrict__ bias, const float* __restrict__ resid,
        float* __restrict__ Cf,
        int M, int N, int K, int lda, int ldb,
        long long bA, long long bB, long long bC,
        float alpha, int permP, int permQ)
{
    extern __shared__ __half smemh[];
    __half* As = smemh;                     // stage stride 5120 halves
    __half* Bs = smemh + GSTAGES * 5120;

    const int z  = blockIdx.z;
    const __half* Ab = A + (long long)z * bA;
    const __half* Bb = B + (long long)z * bB;
    const int m0 = blockIdx.y * 128;
    const int n0 = blockIdx.x * 128;

    const int tid  = threadIdx.x;
    const int lane = tid & 31;
    const int warp = tid >> 5;
    const int warpM = warp >> 1;            // 0..1
    const int warpN = warp & 1;             // 0..1
    const int lr = lane >> 2;               // 0..7
    const int lc = lane & 3;                // 0..3

    // ---- loaders: per thread, 4 x 16B chunks per array per stage ----------
    const __half* Aptr = Ab + (long long)(m0 + tid) * lda;   // row m0+tid
    const unsigned sAu = (unsigned)__cvta_generic_to_shared(As);
    const unsigned sBu = (unsigned)__cvta_generic_to_shared(Bs);
    const unsigned dA0 = sAu + (unsigned)(tid * 80);          // bytes

    const __half* Bptr0 = (BLAYOUT == 0) ? Bb + (long long)(n0 + tid) * ldb : Bb;
    const unsigned dB0 = sBu + (unsigned)(tid * 80);

    const int nkt = K >> 5;

    auto issue = [&](int kt, int slot) {
        const long long ka = (long long)kt * 32;
        const unsigned so = (unsigned)slot * 10240u;          // 5120 halves
        #pragma unroll
        for (int c = 0; c < 4; c++) {
            const __half* g = Aptr + ka + c * 8;
            asm volatile("cp.async.cg.shared.global [%0], [%1], 16;\n"
                         :: "r"(dA0 + so + (unsigned)(c * 16)), "l"(g));
        }
        if (BLAYOUT == 0) {
            #pragma unroll
            for (int c = 0; c < 4; c++) {
                const __half* g = Bptr0 + ka + c * 8;
                asm volatile("cp.async.cg.shared.global [%0], [%1], 16;\n"
                             :: "r"(dB0 + so + (unsigned)(c * 16)), "l"(g));
            }
        } else {
            #pragma unroll
            for (int c = 0; c < 4; c++) {
                const int id = tid * 4 + c;
                const int krow = id >> 4;          // 0..31
                const int ncol = (id & 15) * 8;    // 0..120
                const __half* g = Bb + (ka + krow) * (long long)ldb + n0 + ncol;
                asm volatile("cp.async.cg.shared.global [%0], [%1], 16;\n"
                             :: "r"(sBu + so + (unsigned)(krow * 272 + ncol * 2)), "l"(g));
            }
        }
        asm volatile("cp.async.commit_group;\n");
    };

    float acc[4][8][4];
    #pragma unroll
    for (int a = 0; a < 4; a++)
        #pragma unroll
        for (int b = 0; b < 8; b++)
            #pragma unroll
            for (int c = 0; c < 4; c++) acc[a][b][c] = 0.f;

    #pragma unroll
    for (int s = 0; s < GSTAGES - 1; s++) {
        if (s < nkt) issue(s, s);
        else asm volatile("cp.async.commit_group;\n");
    }

    for (int kt = 0; kt < nkt; kt++) {
        asm volatile("cp.async.wait_group %0;\n" :: "n"(GSTAGES - 2));
        __syncthreads();

        const int nx = kt + GSTAGES - 1;
        if (nx < nkt) issue(nx, nx & (GSTAGES - 1));
        else asm volatile("cp.async.commit_group;\n");

        const __half* Asb = As + (kt & (GSTAGES - 1)) * 5120;
        const __half* Bsb = Bs + (kt & (GSTAGES - 1)) * 5120;

        #pragma unroll
        for (int h = 0; h < 2; h++) {
            const int kk = h * 16;
            // ---- B fragments (8 n-tiles, reused across 4 m-tiles) ----
            unsigned bf[8][2];
            #pragma unroll
            for (int nt = 0; nt < 8; nt++) {
                const int nn = warpN * 64 + nt * 8 + lr;
                if (BLAYOUT == 0) {
                    bf[nt][0] = *(const unsigned*)&Bsb[nn * 40 + kk + 2 * lc];
                    bf[nt][1] = *(const unsigned*)&Bsb[nn * 40 + kk + 2 * lc + 8];
                } else {
                    const int k0 = kk + 2 * lc;
                    unsigned u0 = __half_as_ushort(Bsb[k0 * 136 + nn]);
                    unsigned u1 = __half_as_ushort(Bsb[(k0 + 1) * 136 + nn]);
                    unsigned u2 = __half_as_ushort(Bsb[(k0 + 8) * 136 + nn]);
                    unsigned u3 = __half_as_ushort(Bsb[(k0 + 9) * 136 + nn]);
                    bf[nt][0] = u0 | (u1 << 16);
                    bf[nt][1] = u2 | (u3 << 16);
                }
            }
            #pragma unroll
            for (int mt = 0; mt < 4; mt++) {
                const int r = warpM * 64 + mt * 16 + lr;
                unsigned a0 = *(const unsigned*)&Asb[r * 40 + kk + 2 * lc];
                unsigned a1 = *(const unsigned*)&Asb[(r + 8) * 40 + kk + 2 * lc];
                unsigned a2 = *(const unsigned*)&Asb[r * 40 + kk + 2 * lc + 8];
                unsigned a3 = *(const unsigned*)&Asb[(r + 8) * 40 + kk + 2 * lc + 8];
                #pragma unroll
                for (int nt = 0; nt < 8; nt++) {
                    asm volatile(
                        "mma.sync.aligned.m16n8k16.row.col.f32.f16.f16.f32 "
                        "{%0,%1,%2,%3}, {%4,%5,%6,%7}, {%8,%9}, {%0,%1,%2,%3};"
                        : "+f"(acc[mt][nt][0]), "+f"(acc[mt][nt][1]),
                          "+f"(acc[mt][nt][2]), "+f"(acc[mt][nt][3])
                        : "r"(a0), "r"(a1), "r"(a2), "r"(a3),
                          "r"(bf[nt][0]), "r"(bf[nt][1]));
                }
            }
        }
    }

    // ---- epilogue ----
    __half* Ch = (__half*)Cf;
    #pragma unroll
    for (int mt = 0; mt < 4; mt++) {
        #pragma unroll
        for (int h = 0; h < 2; h++) {
            const int gm = m0 + warpM * 64 + mt * 16 + lr + h * 8;
            const int rm = (permP > 0) ? ((gm % permP) * permQ + gm / permP) : gm;
            const long long base = (long long)z * bC + (long long)rm * N;
            #pragma unroll
            for (int nt = 0; nt < 8; nt++) {
                const int gn = n0 + warpN * 64 + nt * 8 + 2 * lc;
                float v0 = acc[mt][nt][2 * h + 0] * alpha;
                float v1 = acc[mt][nt][2 * h + 1] * alpha;
                if (bias)  { v0 += bias[gn]; v1 += bias[gn + 1]; }
                if (resid) { v0 += resid[base + gn]; v1 += resid[base + gn + 1]; }
                if (ACT == 1) { v0 = gelu_exact(v0); v1 = gelu_exact(v1); }
                else if (ACT == 2) {
                    v0 = 1.0f / (1.0f + expf(-v0));
                    v1 = 1.0f / (1.0f + expf(-v1));
                }
                if (OUTH) {
                    __half2 o; o.x = __float2half(v0); o.y = __float2half(v1);
                    *(__half2*)(&Ch[base + gn]) = o;
                } else {
                    float2 o; o.x = v0; o.y = v1;
                    *(float2*)(&Cf[base + gn]) = o;
                }
            }
        }
    }
}

// ---------------------------------------------------------------------------
// fp32 -> fp16 conversion pass (float4 -> half4)
// ---------------------------------------------------------------------------
__global__ void cvt_h4_k(const float* __restrict__ in, __half* __restrict__ out, int n4)
{
    const int i = blockIdx.x * 256 + threadIdx.x;
    if (i < n4) {
        float4 v = ((const float4*)in)[i];
        __half2 h0, h1;
        h0.x = __float2half(v.x); h0.y = __float2half(v.y);
        h1.x = __float2half(v.z); h1.y = __float2half(v.w);
        ((__half2*)out)[2 * i] = h0;
        ((__half2*)out)[2 * i + 1] = h1;
    }
}

// ---------------------------------------------------------------------------
// LayerNorm over D=1024, fp32 in -> fp16 out
// ---------------------------------------------------------------------------
__global__ void ln_k(const float* __restrict__ x, const float* __restrict__ g,
                     const float* __restrict__ b, __half* __restrict__ y)
{
    const long long row = blockIdx.x;
    const float* xr = x + row * D_MODEL;
    __half* yr = y + row * D_MODEL;
    const int t = threadIdx.x;

    float v[4], s = 0.f, s2 = 0.f;
    #pragma unroll
    for (int i = 0; i < 4; i++) {
        v[i] = xr[t + i * 256];
        s  += v[i];
        s2 += v[i] * v[i];
    }
    #pragma unroll
    for (int o = 16; o > 0; o >>= 1) {
        s  += __shfl_xor_sync(0xFFFFFFFFu, s,  o);
        s2 += __shfl_xor_sync(0xFFFFFFFFu, s2, o);
    }
    __shared__ float shs[8], shs2[8];
    if ((t & 31) == 0) { shs[t >> 5] = s; shs2[t >> 5] = s2; }
    __syncthreads();
    float S = 0.f, S2 = 0.f;
    #pragma unroll
    for (int w = 0; w < 8; w++) { S += shs[w]; S2 += shs2[w]; }

    const float mean = S * (1.0f / D_MODEL);
    const float var  = S2 * (1.0f / D_MODEL) - mean * mean;
    const float inv  = rsqrtf(var + 1e-5f);
    #pragma unroll
    for (int i = 0; i < 4; i++) {
        const int c = t + i * 256;
        yr[c] = __float2half((v[i] - mean) * inv * g[c] + b[c]);
    }
}

// ---------------------------------------------------------------------------
// Row softmax fp32 in -> fp16 out (optionally + log(prev_mask + 1e-6))
// ---------------------------------------------------------------------------
__global__ void softmax_k(const float* __restrict__ s, const float* __restrict__ pm,
                          __half* __restrict__ outh, int cols)
{
    const long long row = blockIdx.x;
    const float* r = s + row * cols;
    __half* ro = outh + row * cols;
    const float* pmr = pm ? pm + row * cols : nullptr;
    const int t = threadIdx.x;
    const int nc = cols >> 8;

    float lv[16];
    float mx = -1e30f;
    for (int i = 0; i < nc; i++) {
        float v = r[t + (i << 8)];
        if (pmr) v += logf(pmr[t + (i << 8)] + 1e-6f);
        lv[i] = v;
        mx = fmaxf(mx, v);
    }
    #pragma unroll
    for (int o = 16; o > 0; o >>= 1)
        mx = fmaxf(mx, __shfl_xor_sync(0xFFFFFFFFu, mx, o));
    __shared__ float shm[8], shsum[8];
    if ((t & 31) == 0) shm[t >> 5] = mx;
    __syncthreads();
    float MX = shm[0];
    #pragma unroll
    for (int w = 1; w < 8; w++) MX = fmaxf(MX, shm[w]);

    float sum = 0.f;
    for (int i = 0; i < nc; i++) {
        const float e = expf(lv[i] - MX);
        lv[i] = e;
        sum += e;
    }
    #pragma unroll
    for (int o = 16; o > 0; o >>= 1)
        sum += __shfl_xor_sync(0xFFFFFFFFu, sum, o);
    if ((t & 31) == 0) shsum[t >> 5] = sum;
    __syncthreads();
    float SUM = 0.f;
    #pragma unroll
    for (int w = 0; w < 8; w++) SUM += shsum[w];

    const float inv = 1.0f / SUM;
    for (int i = 0; i < nc; i++)
        ro[t + (i << 8)] = __float2half(lv[i] * inv);
}

// ---------------------------------------------------------------------------
// Repack kernels (fp32 in -> fp16 out)
// ---------------------------------------------------------------------------
__global__ void repack_qkv_k(const float* __restrict__ qkv, __half* __restrict__ pack)
{
    const long long gid = (long long)blockIdx.x * 256 + threadIdx.x;
    const int d   = gid & 127;
    const int l   = (gid >> 7) & 255;
    const int bh  = (gid >> 15) & 63;
    const int sec = (int)(gid >> 21);
    const int b = bh >> 3, h = bh & 7;
    const long long in = (long long)(l * BATCH + b) * (3 * D_MODEL)
                         + sec * D_MODEL + h * HDIM + d;
    pack[gid] = __float2half(qkv[in]);
}

__global__ void repack_o_k(const float* __restrict__ o, __half* __restrict__ out)
{
    const long long gid = (long long)blockIdx.x * 256 + threadIdx.x;
    const int c = gid & 1023;
    const int m = (int)(gid >> 10);
    const int l = m >> 3, b = m & 7;
    const int h = c >> 7, d = c & 127;
    out[gid] = __float2half(o[((long long)(b * 8 + h) * 256 + l) * 128 + d]);
}

__global__ void repack_qmask_k(const float* __restrict__ q, __half* __restrict__ out)
{
    const long long gid = (long long)blockIdx.x * 256 + threadIdx.x;
    const int d = gid & 1023;
    const int m = (int)(gid >> 10);
    const int b = m >> 8, qq = m & 255;
    out[gid] = __float2half(q[(long long)(qq * 8 + b) * 1024 + d]);
}

// ---------------------------------------------------------------------------
// kernel_launch
// ---------------------------------------------------------------------------
extern "C" void kernel_launch(void* const* d_in, const int* in_sizes, int n_in,
                              void* d_out, int out_size)
{
    const float* query    = (const float*)d_in[0];
    const float* memory   = (const float*)d_in[1];
    const float* prevmask = (const float*)d_in[2];
    const float* sa_in_w  = (const float*)d_in[5];
    const float* sa_in_b  = (const float*)d_in[6];
    const float* sa_out_w = (const float*)d_in[7];
    const float* sa_out_b = (const float*)d_in[8];
    const float* ln1_g = (const float*)d_in[9];
    const float* ln1_b = (const float*)d_in[10];
    const float* ln2_g = (const float*)d_in[11];
    const float* ln2_b = (const float*)d_in[12];
    const float* ln3_g = (const float*)d_in[13];
    const float* ln3_b = (const float*)d_in[14];
    const float* wq = (const float*)d_in[15];
    const float* bq = (const float*)d_in[16];
    const float* wk = (const float*)d_in[17];
    const float* bk = (const float*)d_in[18];
    const float* wv = (const float*)d_in[19];
    const float* bv = (const float*)d_in[20];
    const float* wo = (const float*)d_in[21];
    const float* bo = (const float*)d_in[22];
    const float* w1 = (const float*)d_in[23];
    const float* b1 = (const float*)d_in[24];
    const float* w2 = (const float*)d_in[25];
    const float* b2 = (const float*)d_in[26];
    const float* mask_w = (const float*)d_in[27];
    const float* mask_b = (const float*)d_in[28];

    float* scr = nullptr;
    cudaGetSymbolAddress((void**)&scr, g_scratch);

    __half* gx   = (__half*)(scr + OFF_X);
    float*  gqkv = scr + OFF_QKV;
    __half* gq   = (__half*)(scr + OFF_PACK);
    __half* gk   = gq + 2097152LL;
    __half* gv   = gq + 4194304LL;
    float*  gsc  = scr + OFF_SCORES;
    float*  go   = scr + OFF_O;
    __half* gorep = (__half*)(scr + OFF_OREP);
    float*  gq1  = scr + OFF_Q1;
    __half* gQc  = (__half*)(scr + OFF_QC);
    __half* gK   = (__half*)(scr + OFF_K);
    __half* gV   = (__half*)(scr + OFF_V);
    float*  gq2  = scr + OFF_Q2;
    __half* gh   = (__half*)(scr + OFF_H);
    __half* gqm  = (__half*)(scr + OFF_QM);
    __half* gsch = (__half*)(scr + OFF_SCH);
    __half* goh  = (__half*)(scr + OFF_GOH);
    __half* wh   = (__half*)(scr + OFF_WH);
    __half* memh = (__half*)(scr + OFF_MEMH);

    __half* c_sa_in_w  = wh + H_SAIN;
    __half* c_sa_out_w = wh + H_SAOUT;
    __half* c_wq = wh + H_Q;
    __half* c_wk = wh + H_K;
    __half* c_wv = wh + H_V;
    __half* c_wo = wh + H_O;
    __half* c_w1 = wh + H_1;
    __half* c_w2 = wh + H_2;
    __half* c_mask_w = wh + H_MASK;

    float* out_q = (float*)d_out;
    float* out_m = out_q + (long long)M_TOK * D_MODEL;

    const float inv_sqrt_hd = 0.088388347648318447f;
    const float inv_sqrt_d  = 0.03125f;

    cudaFuncSetAttribute(gemm_tc<0,0,0>, cudaFuncAttributeMaxDynamicSharedMemorySize, GSMEM_BYTES);
    cudaFuncSetAttribute(gemm_tc<0,0,1>, cudaFuncAttributeMaxDynamicSharedMemorySize, GSMEM_BYTES);
    cudaFuncSetAttribute(gemm_tc<1,0,0>, cudaFuncAttributeMaxDynamicSharedMemorySize, GSMEM_BYTES);
    cudaFuncSetAttribute(gemm_tc<1,0,1>, cudaFuncAttributeMaxDynamicSharedMemorySize, GSMEM_BYTES);
    cudaFuncSetAttribute(gemm_tc<0,1,1>, cudaFuncAttributeMaxDynamicSharedMemorySize, GSMEM_BYTES);
    cudaFuncSetAttribute(gemm_tc<0,2,0>, cudaFuncAttributeMaxDynamicSharedMemorySize, GSMEM_BYTES);

    // --- 0. fp16 conversion: weights + memory ---
    cvt_h4_k<<<3072, 256>>>(sa_in_w, c_sa_in_w, 786432);
    cvt_h4_k<<<1024, 256>>>(sa_out_w, c_sa_out_w, 262144);
    cvt_h4_k<<<1024, 256>>>(wq, c_wq, 262144);
    cvt_h4_k<<<1024, 256>>>(wk, c_wk, 262144);
    cvt_h4_k<<<1024, 256>>>(wv, c_wv, 262144);
    cvt_h4_k<<<1024, 256>>>(wo, c_wo, 262144);
    cvt_h4_k<<<4096, 256>>>(w1, c_w1, 1048576);
    cvt_h4_k<<<4096, 256>>>(w2, c_w2, 1048576);
    cvt_h4_k<<<4096, 256>>>(mask_w, c_mask_w, 1048576);
    cvt_h4_k<<<32768, 256>>>(memory, memh, 8388608);

    // 1. ln1(query) -> half
    ln_k<<<M_TOK, 256>>>(query, ln1_g, ln1_b, gx);

    // 2. QKV projection -> fp32
    gemm_tc<0,0,0><<<dim3(24,16,1), 128, GSMEM_BYTES>>>(gx, c_sa_in_w, sa_in_b, nullptr, gqkv,
        M_TOK, 3*D_MODEL, D_MODEL, D_MODEL, D_MODEL, 0, 0, 0, 1.0f, 0, 0);

    // 3. pack q,k,v -> half
    repack_qkv_k<<<24576, 256>>>(gqkv, gq);

    // 4. self-attn scores (batched 64) -> fp32
    gemm_tc<0,0,0><<<dim3(2,2,64), 128, GSMEM_BYTES>>>(gq, gk, nullptr, nullptr, gsc,
        NQ, NQ, HDIM, HDIM, HDIM, 256LL*128, 256LL*128, 256LL*256,
        inv_sqrt_hd, 0, 0);

    // 5. softmax -> half
    softmax_k<<<64*256, 256>>>(gsc, nullptr, gsch, 256);

    // 6. o = attn @ v -> fp32
    gemm_tc<1,0,0><<<dim3(1,2,64), 128, GSMEM_BYTES>>>(gsch, gv, nullptr, nullptr, go,
        NQ, HDIM, NQ, NQ, HDIM, 256LL*256, 256LL*128, 256LL*128, 1.0f, 0, 0);

    // 7. repack o -> half
    repack_o_k<<<8192, 256>>>(go, gorep);

    // 8. self out-proj + residual -> fp32
    gemm_tc<0,0,0><<<dim3(8,16,1), 128, GSMEM_BYTES>>>(gorep, c_sa_out_w, sa_out_b, query, gq1,
        M_TOK, D_MODEL, D_MODEL, D_MODEL, D_MODEL, 0, 0, 0, 1.0f, 0, 0);

    // 9. ln2 -> half
    ln_k<<<M_TOK, 256>>>(gq1, ln2_g, ln2_b, gx);

    // 10. Q proj -> half [B,NQ,D]
    gemm_tc<0,0,1><<<dim3(8,16,1), 128, GSMEM_BYTES>>>(gx, c_wq, bq, nullptr, (float*)gQc,
        M_TOK, D_MODEL, D_MODEL, D_MODEL, D_MODEL, 0, 0, 0, 1.0f, 8, 256);

    // 11/12. K,V proj -> half [B,S,D]
    gemm_tc<0,0,1><<<dim3(8,256,1), 128, GSMEM_BYTES>>>(memh, c_wk, bk, nullptr, (float*)gK,
        M_MEM, D_MODEL, D_MODEL, D_MODEL, D_MODEL, 0, 0, 0, 1.0f, 8, 4096);
    gemm_tc<0,0,1><<<dim3(8,256,1), 128, GSMEM_BYTES>>>(memh, c_wv, bv, nullptr, (float*)gV,
        M_MEM, D_MODEL, D_MODEL, D_MODEL, D_MODEL, 0, 0, 0, 1.0f, 8, 4096);

    // 13. cross scores -> fp32
    gemm_tc<0,0,0><<<dim3(32,2,8), 128, GSMEM_BYTES>>>(gQc, gK, nullptr, nullptr, gsc,
        NQ, SEQ_S, D_MODEL, D_MODEL, D_MODEL,
        256LL*1024, 4096LL*1024, 256LL*4096, inv_sqrt_d, 0, 0);

    // 14. softmax + log(prev_mask) -> half
    softmax_k<<<BATCH*NQ, 256>>>(gsc, prevmask, gsch, SEQ_S);

    // 15. attn_out = attn @ V -> half
    gemm_tc<1,0,1><<<dim3(8,2,8), 128, GSMEM_BYTES>>>(gsch, gV, nullptr, nullptr, (float*)goh,
        NQ, D_MODEL, SEQ_S, SEQ_S, D_MODEL,
        256LL*4096, 4096LL*1024, 256LL*1024, 1.0f, 0, 0);

    // 16. cross out-proj + residual -> fp32 [NQ,B,D]
    gemm_tc<0,0,0><<<dim3(8,16,1), 128, GSMEM_BYTES>>>(goh, c_wo, bo, gq1, gq2,
        M_TOK, D_MODEL, D_MODEL, D_MODEL, D_MODEL, 0, 0, 0, 1.0f, 256, 8);

    // 17. ln3 -> half
    ln_k<<<M_TOK, 256>>>(gq2, ln3_g, ln3_b, gx);

    // 18. FFN1 + GELU -> half
    gemm_tc<0,1,1><<<dim3(32,16,1), 128, GSMEM_BYTES>>>(gx, c_w1, b1, nullptr, (float*)gh,
        M_TOK, FF_DIM, D_MODEL, D_MODEL, D_MODEL, 0, 0, 0, 1.0f, 0, 0);

    // 19. FFN2 + residual -> final query (fp32)
    gemm_tc<0,0,0><<<dim3(8,16,1), 128, GSMEM_BYTES>>>(gh, c_w2, b2, gq2, out_q,
        M_TOK, D_MODEL, FF_DIM, FF_DIM, FF_DIM, 0, 0, 0, 1.0f, 0, 0);

    // 20. gather final query -> half [B,NQ,D]
    repack_qmask_k<<<8192, 256>>>(out_q, gqm);

    // 21. mask logits + sigmoid -> fp32
    gemm_tc<0,2,0><<<dim3(32,16,1), 128, GSMEM_BYTES>>>(gqm, c_mask_w, mask_b, nullptr, out_m,
        M_TOK, SEQ_S, D_MODEL, D_MODEL, D_MODEL, 0, 0, 0, 1.0f, 0, 0);
}

// round 11
// speedup vs baseline: 1.2571x; 1.2571x over previous
#include <cuda_runtime.h>
#include <math.h>

// ---------------------------------------------------------------------------
// Problem constants
// ---------------------------------------------------------------------------
#define D_MODEL 1024
#define NHEAD   8
#define HDIM    128
#define NQ      256
#define BATCH   8
#define SEQ_S   4096
#define FF_DIM  4096
#define M_TOK   (NQ*BATCH)       // 2048
#define M_MEM   (SEQ_S*BATCH)    // 32768

// ---------------------------------------------------------------------------
// Scratch (offsets in floats)
// ---------------------------------------------------------------------------
#define OFF_X      0LL                       // ln out [2048,1024]
#define OFF_PACK   2097152LL                 // q,k,v packed [3][64][256][128]
#define OFF_SCORES 8388608LL                 // fp32 scores (8.39M)
#define OFF_OREP   16777216LL                // attn-out repacked [2048,1024]
#define OFF_Q1     18874368LL
#define OFF_QC     20971520LL                // cross Q [8,256,1024]
#define OFF_KV     23068672LL                // fused K|V [8][4096][2048]
#define OFF_Q2     90177536LL
#define OFF_H      92274688LL                // FFN hidden [2048,4096]
#define OFF_QM     100663296LL               // query gathered [B,NQ,D]
#define OFF_WKV    102760448LL               // concat wk|wv [2048,1024]
#define OFF_BKV    104857600LL               // concat bias [2048]
#define SCRATCH_TOTAL 104859648LL

__device__ float g_scratch[SCRATCH_TOTAL];

// ---------------------------------------------------------------------------
// Helpers
// ---------------------------------------------------------------------------
__device__ __forceinline__ float gelu_exact(float x) {
    return 0.5f * x * (1.0f + erff(x * 0.70710678118654752f));
}

// ---------------------------------------------------------------------------
// tf32 tensor-core batched GEMM, 4-stage cp.async pipeline.
// 128 threads, 4 warps, warp tile 64x64, CTA tile 128x128x16.
//   C = act( alpha * A @ op(B) + bias + resid )
//   A fp32 row-major [M,K] (raw fp32; HW mma truncates to tf32).
//   BLAYOUT 0: B is [N,K] (A@B^T). BLAYOUT 1: B is [K,N].
//   ACT: 0 none, 1 gelu, 2 sigmoid.
//   PK:  0 = normal epilogue (permP/permQ row remap on C; optional dual
//            store to C2 with fixed (m%8)*256+m/8 remap)
//        1 = QKV head-pack epilogue (N=3072, writes pack[sec][b*8+h][l][d])
//        2 = self-AV o-pack epilogue (z=b*8+h, writes [l*8+b][h*128+d])
// Dynamic smem: 4 stages * (2560 + 2560) floats = 81920 B.
// ---------------------------------------------------------------------------
#define GSTAGES 4
#define GSMEM_BYTES (GSTAGES * 2560 * 2 * 4)

template<int BLAYOUT, int ACT, int PK>
__global__ void __launch_bounds__(128, 2)
gemm_tc(const float* __restrict__ A, const float* __restrict__ B,
        const float* __restrict__ bias, const float* __restrict__ resid,
        float* __restrict__ C, float* __restrict__ C2,
        int M, int N, int K, int lda, int ldb,
        long long bA, long long bB, long long bC,
        float alpha, int permP, int permQ)
{
    extern __shared__ float smemf[];
    float* As = smemf;                      // [GSTAGES][128][20]
    float* Bs = smemf + GSTAGES * 2560;     // [GSTAGES][128][20] or [16][136]

    const int z  = blockIdx.z;
    const float* Ab = A + (long long)z * bA;
    const float* Bb = B + (long long)z * bB;
    const int m0 = blockIdx.y * 128;
    const int n0 = blockIdx.x * 128;

    const int tid  = threadIdx.x;
    const int lane = tid & 31;
    const int warp = tid >> 5;
    const int warpM = warp >> 1;            // 0..1
    const int warpN = warp & 1;             // 0..1
    const int lr = lane >> 2;               // 0..7
    const int lc = lane & 3;                // 0..3

    const int a_r0 = tid >> 2;              // 0..31 (+32*i)
    const int a_kq = (tid & 3) * 4;
    const float* Aptr = Ab + (long long)(m0 + a_r0) * lda + a_kq;

    const float* Bptr;
    int b1_k0 = 0, b1_nq = 0;
    if (BLAYOUT == 0) {
        Bptr = Bb + (long long)(n0 + a_r0) * ldb + a_kq;
    } else {
        b1_k0 = tid >> 5;
        b1_nq = (tid & 31) * 4;
        Bptr = Bb + (long long)b1_k0 * ldb + n0 + b1_nq;
    }

    const unsigned sAu = (unsigned)__cvta_generic_to_shared(As);
    const unsigned sBu = (unsigned)__cvta_generic_to_shared(Bs);
    const unsigned dA0 = sAu + (unsigned)(a_r0 * 20 + a_kq) * 4u;
    const unsigned dB0 = (BLAYOUT == 0)
        ? sBu + (unsigned)(a_r0 * 20 + a_kq) * 4u
        : sBu + (unsigned)(b1_k0 * 136 + b1_nq) * 4u;

    const int nkt = K >> 4;

    auto issue = [&](int kt, int slot) {
        const long long ka = (long long)kt * 16;
        const unsigned so = (unsigned)slot * 2560u * 4u;
        #pragma unroll
        for (int i = 0; i < 4; i++) {
            const float* g = Aptr + (long long)i * 32 * lda + ka;
            unsigned d = dA0 + so + (unsigned)(i * 32 * 20) * 4u;
            asm volatile("cp.async.cg.shared.global [%0], [%1], 16;\n" :: "r"(d), "l"(g));
        }
        if (BLAYOUT == 0) {
            #pragma unroll
            for (int i = 0; i < 4; i++) {
                const float* g = Bptr + (long long)i * 32 * ldb + ka;
                unsigned d = dB0 + so + (unsigned)(i * 32 * 20) * 4u;
                asm volatile("cp.async.cg.shared.global [%0], [%1], 16;\n" :: "r"(d), "l"(g));
            }
        } else {
            #pragma unroll
            for (int i = 0; i < 4; i++) {
                const float* g = Bptr + (ka + (long long)i * 4) * ldb;
                unsigned d = dB0 + so + (unsigned)(i * 4 * 136) * 4u;
                asm volatile("cp.async.cg.shared.global [%0], [%1], 16;\n" :: "r"(d), "l"(g));
            }
        }
        asm volatile("cp.async.commit_group;\n");
    };

    float acc[4][8][4];
    #pragma unroll
    for (int a = 0; a < 4; a++)
        #pragma unroll
        for (int b = 0; b < 8; b++)
            #pragma unroll
            for (int c = 0; c < 4; c++) acc[a][b][c] = 0.f;

    #pragma unroll
    for (int s = 0; s < GSTAGES - 1; s++) {
        if (s < nkt) issue(s, s);
        else asm volatile("cp.async.commit_group;\n");
    }

    for (int kt = 0; kt < nkt; kt++) {
        asm volatile("cp.async.wait_group %0;\n" :: "n"(GSTAGES - 2));
        __syncthreads();

        const int nx = kt + GSTAGES - 1;
        if (nx < nkt) issue(nx, nx & (GSTAGES - 1));
        else asm volatile("cp.async.commit_group;\n");

        const float* Asb = As + (kt & (GSTAGES - 1)) * 2560;
        const float* Bsb = Bs + (kt & (GSTAGES - 1)) * 2560;

        #pragma unroll
        for (int k8 = 0; k8 < 2; k8++) {
            const int c = k8 * 8 + lc;
            unsigned bf[8][2];
            #pragma unroll
            for (int nt = 0; nt < 8; nt++) {
                if (BLAYOUT == 0) {
                    const int nn = warpN*64 + nt*8 + lr;
                    bf[nt][0] = __float_as_uint(Bsb[nn*20 + c]);
                    bf[nt][1] = __float_as_uint(Bsb[nn*20 + c + 4]);
                } else {
                    const int kk = k8*8 + lc;
                    const int nn = warpN*64 + nt*8 + lr;
                    bf[nt][0] = __float_as_uint(Bsb[kk*136 + nn]);
                    bf[nt][1] = __float_as_uint(Bsb[(kk+4)*136 + nn]);
                }
            }
            #pragma unroll
            for (int mt = 0; mt < 4; mt++) {
                const int r = warpM*64 + mt*16 + lr;
                unsigned a0 = __float_as_uint(Asb[r*20 + c]);
                unsigned a1 = __float_as_uint(Asb[(r+8)*20 + c]);
                unsigned a2 = __float_as_uint(Asb[r*20 + c + 4]);
                unsigned a3 = __float_as_uint(Asb[(r+8)*20 + c + 4]);
                #pragma unroll
                for (int nt = 0; nt < 8; nt++) {
                    asm volatile(
                        "mma.sync.aligned.m16n8k8.row.col.f32.tf32.tf32.f32 "
                        "{%0,%1,%2,%3}, {%4,%5,%6,%7}, {%8,%9}, {%0,%1,%2,%3};"
                        : "+f"(acc[mt][nt][0]), "+f"(acc[mt][nt][1]),
                          "+f"(acc[mt][nt][2]), "+f"(acc[mt][nt][3])
                        : "r"(a0), "r"(a1), "r"(a2), "r"(a3),
                          "r"(bf[nt][0]), "r"(bf[nt][1]));
                }
            }
        }
    }

    // ---- epilogue ----
    #pragma unroll
    for (int mt = 0; mt < 4; mt++) {
        #pragma unroll
        for (int h = 0; h < 2; h++) {
            const int gm = m0 + warpM*64 + mt*16 + lr + h*8;
            #pragma unroll
            for (int nt = 0; nt < 8; nt++) {
                const int gn = n0 + warpN*64 + nt*8 + 2*lc;
                float v0 = acc[mt][nt][2*h+0] * alpha;
                float v1 = acc[mt][nt][2*h+1] * alpha;
                if (PK != 2) {
                    if (bias) { v0 += bias[gn]; v1 += bias[gn+1]; }
                }
                if (PK == 1) {
                    // QKV head-pack: row gm = l*8+b, col gn = sec*1024+hh*128+d
                    const int b = gm & 7, l = gm >> 3;
                    const int sec = gn >> 10, hh = (gn >> 7) & 7, d = gn & 127;
                    const long long idx = (long long)sec * 2097152LL
                        + ((long long)(b*8 + hh) * 256 + l) * 128 + d;
                    float2 o; o.x = v0; o.y = v1;
                    *(float2*)(&C[idx]) = o;
                } else if (PK == 2) {
                    // o-pack: z=b*8+hh, row gm=l, col gn=d -> [l*8+b][hh*128+d]
                    const int b = z >> 3, hh = z & 7;
                    const long long idx = ((long long)(gm*8 + b)) * 1024 + hh*128 + gn;
                    float2 o; o.x = v0; o.y = v1;
                    *(float2*)(&C[idx]) = o;
                } else {
                    const int rm = (permP > 0) ? ((gm % permP) * permQ + gm / permP) : gm;
                    const long long base = (long long)z * bC + (long long)rm * N;
                    if (resid) { v0 += resid[base + gn]; v1 += resid[base + gn + 1]; }
                    if (ACT == 1) { v0 = gelu_exact(v0); v1 = gelu_exact(v1); }
                    else if (ACT == 2) {
                        v0 = 1.0f / (1.0f + expf(-v0));
                        v1 = 1.0f / (1.0f + expf(-v1));
                    }
                    float2 o; o.x = v0; o.y = v1;
                    *(float2*)(&C[base + gn]) = o;
                    if (C2) {
                        const int r2 = (gm & 7) * 256 + (gm >> 3);
                        *(float2*)(&C2[(long long)r2 * N + gn]) = o;
                    }
                }
            }
        }
    }
}

// ---------------------------------------------------------------------------
// Concat wk|wv weights + biases into fused buffers (float4)
// ---------------------------------------------------------------------------
__global__ void concat_kv_k(const float* __restrict__ wk, const float* __restrict__ wv,
                            const float* __restrict__ bk, const float* __restrict__ bv,
                            float* __restrict__ w, float* __restrict__ b)
{
    const int i = blockIdx.x * 256 + threadIdx.x;
    if (i < 524288) {
        // weights: first 262144 float4 = wk, next = wv
        float4 v = (i < 262144) ? ((const float4*)wk)[i] : ((const float4*)wv)[i - 262144];
        ((float4*)w)[i] = v;
    } else if (i < 524800) {
        const int j = i - 524288;   // 0..511 float4s of bias
        float4 v = (j < 256) ? ((const float4*)bk)[j] : ((const float4*)bv)[j - 256];
        ((float4*)b)[j] = v;
    }
}

// ---------------------------------------------------------------------------
// LayerNorm over D=1024 (fp32 out)
// ---------------------------------------------------------------------------
__global__ void ln_k(const float* __restrict__ x, const float* __restrict__ g,
                     const float* __restrict__ b, float* __restrict__ y)
{
    const long long row = blockIdx.x;
    const float* xr = x + row * D_MODEL;
    float* yr = y + row * D_MODEL;
    const int t = threadIdx.x;

    float v[4], s = 0.f, s2 = 0.f;
    #pragma unroll
    for (int i = 0; i < 4; i++) {
        v[i] = xr[t + i * 256];
        s  += v[i];
        s2 += v[i] * v[i];
    }
    #pragma unroll
    for (int o = 16; o > 0; o >>= 1) {
        s  += __shfl_xor_sync(0xFFFFFFFFu, s,  o);
        s2 += __shfl_xor_sync(0xFFFFFFFFu, s2, o);
    }
    __shared__ float shs[8], shs2[8];
    if ((t & 31) == 0) { shs[t >> 5] = s; shs2[t >> 5] = s2; }
    __syncthreads();
    float S = 0.f, S2 = 0.f;
    #pragma unroll
    for (int w = 0; w < 8; w++) { S += shs[w]; S2 += shs2[w]; }

    const float mean = S * (1.0f / D_MODEL);
    const float var  = S2 * (1.0f / D_MODEL) - mean * mean;
    const float inv  = rsqrtf(var + 1e-5f);
    #pragma unroll
    for (int i = 0; i < 4; i++) {
        const int c = t + i * 256;
        yr[c] = (v[i] - mean) * inv * g[c] + b[c];
    }
}

// ---------------------------------------------------------------------------
// Row softmax in-place fp32 (optionally + log(prev_mask + 1e-6))
// ---------------------------------------------------------------------------
__global__ void softmax_k(float* __restrict__ s, const float* __restrict__ pm, int cols)
{
    const long long row = blockIdx.x;
    float* r = s + row * cols;
    const float* pmr = pm ? pm + row * cols : nullptr;
    const int t = threadIdx.x;
    const int nc = cols >> 8;

    float lv[16];
    float mx = -1e30f;
    for (int i = 0; i < nc; i++) {
        float v = r[t + (i << 8)];
        if (pmr) v += logf(pmr[t + (i << 8)] + 1e-6f);
        lv[i] = v;
        mx = fmaxf(mx, v);
    }
    #pragma unroll
    for (int o = 16; o > 0; o >>= 1)
        mx = fmaxf(mx, __shfl_xor_sync(0xFFFFFFFFu, mx, o));
    __shared__ float shm[8], shsum[8];
    if ((t & 31) == 0) shm[t >> 5] = mx;
    __syncthreads();
    float MX = shm[0];
    #pragma unroll
    for (int w = 1; w < 8; w++) MX = fmaxf(MX, shm[w]);

    float sum = 0.f;
    for (int i = 0; i < nc; i++) {
        const float e = expf(lv[i] - MX);
        lv[i] = e;
        sum += e;
    }
    #pragma unroll
    for (int o = 16; o > 0; o >>= 1)
        sum += __shfl_xor_sync(0xFFFFFFFFu, sum, o);
    if ((t & 31) == 0) shsum[t >> 5] = sum;
    __syncthreads();
    float SUM = 0.f;
    #pragma unroll
    for (int w = 0; w < 8; w++) SUM += shsum[w];

    const float inv = 1.0f / SUM;
    for (int i = 0; i < nc; i++) r[t + (i << 8)] = lv[i] * inv;
}

// ---------------------------------------------------------------------------
// kernel_launch
// ---------------------------------------------------------------------------
extern "C" void kernel_launch(void* const* d_in, const int* in_sizes, int n_in,
                              void* d_out, int out_size)
{
    const float* query    = (const float*)d_in[0];
    const float* memory   = (const float*)d_in[1];
    const float* prevmask = (const float*)d_in[2];
    const float* sa_in_w  = (const float*)d_in[5];
    const float* sa_in_b  = (const float*)d_in[6];
    const float* sa_out_w = (const float*)d_in[7];
    const float* sa_out_b = (const float*)d_in[8];
    const float* ln1_g = (const float*)d_in[9];
    const float* ln1_b = (const float*)d_in[10];
    const float* ln2_g = (const float*)d_in[11];
    const float* ln2_b = (const float*)d_in[12];
    const float* ln3_g = (const float*)d_in[13];
    const float* ln3_b = (const float*)d_in[14];
    const float* wq = (const float*)d_in[15];
    const float* bq = (const float*)d_in[16];
    const float* wk = (const float*)d_in[17];
    const float* bk = (const float*)d_in[18];
    const float* wv = (const float*)d_in[19];
    const float* bv = (const float*)d_in[20];
    const float* wo = (const float*)d_in[21];
    const float* bo = (const float*)d_in[22];
    const float* w1 = (const float*)d_in[23];
    const float* b1 = (const float*)d_in[24];
    const float* w2 = (const float*)d_in[25];
    const float* b2 = (const float*)d_in[26];
    const float* mask_w = (const float*)d_in[27];
    const float* mask_b = (const float*)d_in[28];

    float* scr = nullptr;
    cudaGetSymbolAddress((void**)&scr, g_scratch);

    float* gx    = scr + OFF_X;
    float* gq    = scr + OFF_PACK;                 // pack base (q)
    float* gv    = scr + OFF_PACK + 4194304LL;     // v section
    float* gk    = scr + OFF_PACK + 2097152LL;     // k section
    float* gsc   = scr + OFF_SCORES;
    float* gorep = scr + OFF_OREP;
    float* gq1   = scr + OFF_Q1;
    float* gQc   = scr + OFF_QC;
    float* gKV   = scr + OFF_KV;                   // [8][4096][2048] K|V
    float* gq2   = scr + OFF_Q2;
    float* gh    = scr + OFF_H;
    float* gqm   = scr + OFF_QM;
    float* gwkv  = scr + OFF_WKV;
    float* gbkv  = scr + OFF_BKV;

    float* out_q = (float*)d_out;
    float* out_m = out_q + (long long)M_TOK * D_MODEL;

    const float inv_sqrt_hd = 0.088388347648318447f;
    const float inv_sqrt_d  = 0.03125f;

    cudaFuncSetAttribute(gemm_tc<0,0,0>, cudaFuncAttributeMaxDynamicSharedMemorySize, GSMEM_BYTES);
    cudaFuncSetAttribute(gemm_tc<0,0,1>, cudaFuncAttributeMaxDynamicSharedMemorySize, GSMEM_BYTES);
    cudaFuncSetAttribute(gemm_tc<1,0,2>, cudaFuncAttributeMaxDynamicSharedMemorySize, GSMEM_BYTES);
    cudaFuncSetAttribute(gemm_tc<1,0,0>, cudaFuncAttributeMaxDynamicSharedMemorySize, GSMEM_BYTES);
    cudaFuncSetAttribute(gemm_tc<0,1,0>, cudaFuncAttributeMaxDynamicSharedMemorySize, GSMEM_BYTES);
    cudaFuncSetAttribute(gemm_tc<0,2,0>, cudaFuncAttributeMaxDynamicSharedMemorySize, GSMEM_BYTES);

    // 0. concat wk|wv into fused KV weight/bias
    concat_kv_k<<<2051, 256>>>(wk, wv, bk, bv, gwkv, gbkv);

    // 1. ln1(query)
    ln_k<<<M_TOK, 256>>>(query, ln1_g, ln1_b, gx);

    // 2. QKV projection with fused head-pack epilogue (PK=1)
    gemm_tc<0,0,1><<<dim3(24,16,1), 128, GSMEM_BYTES>>>(gx, sa_in_w, sa_in_b, nullptr,
        gq, nullptr, M_TOK, 3*D_MODEL, D_MODEL, D_MODEL, D_MODEL, 0, 0, 0, 1.0f, 0, 0);

    // 3. self-attn scores (batched 64)
    gemm_tc<0,0,0><<<dim3(2,2,64), 128, GSMEM_BYTES>>>(gq, gk, nullptr, nullptr,
        gsc, nullptr, NQ, NQ, HDIM, HDIM, HDIM, 256LL*128, 256LL*128, 256LL*256,
        inv_sqrt_hd, 0, 0);

    // 4. softmax
    softmax_k<<<64*256, 256>>>(gsc, nullptr, 256);

    // 5. o = attn @ v with fused o-pack epilogue (PK=2) -> gorep [2048,1024]
    gemm_tc<1,0,2><<<dim3(1,2,64), 128, GSMEM_BYTES>>>(gsc, gv, nullptr, nullptr,
        gorep, nullptr, NQ, HDIM, NQ, NQ, HDIM, 256LL*256, 256LL*128, 0, 1.0f, 0, 0);

    // 6. self out-proj + residual
    gemm_tc<0,0,0><<<dim3(8,16,1), 128, GSMEM_BYTES>>>(gorep, sa_out_w, sa_out_b, query,
        gq1, nullptr, M_TOK, D_MODEL, D_MODEL, D_MODEL, D_MODEL, 0, 0, 0, 1.0f, 0, 0);

    // 7. ln2
    ln_k<<<M_TOK, 256>>>(gq1, ln2_g, ln2_b, gx);

    // 8. Q proj -> [B,NQ,D]
    gemm_tc<0,0,0><<<dim3(8,16,1), 128, GSMEM_BYTES>>>(gx, wq, bq, nullptr,
        gQc, nullptr, M_TOK, D_MODEL, D_MODEL, D_MODEL, D_MODEL, 0, 0, 0, 1.0f, 8, 256);

    // 9. fused K|V projection: [32768,2048] from raw memory -> gKV [8][4096][2048]
    gemm_tc<0,0,0><<<dim3(16,256,1), 128, GSMEM_BYTES>>>(memory, gwkv, gbkv, nullptr,
        gKV, nullptr, M_MEM, 2048, D_MODEL, D_MODEL, D_MODEL, 0, 0, 0, 1.0f, 8, 4096);

    // 10. cross scores: Q @ K'^T (K' = gKV cols 0..1023, row stride 2048)
    gemm_tc<0,0,0><<<dim3(32,2,8), 128, GSMEM_BYTES>>>(gQc, gKV, nullptr, nullptr,
        gsc, nullptr, NQ, SEQ_S, D_MODEL, D_MODEL, 2048,
        256LL*1024, 4096LL*2048, 256LL*4096, inv_sqrt_d, 0, 0);

    // 11. softmax + log(prev_mask)
    softmax_k<<<BATCH*NQ, 256>>>(gsc, prevmask, SEQ_S);

    // 12. attn_out = attn @ V' (V' = gKV cols 1024..2047) -> gorep [8][256][1024]
    gemm_tc<1,0,0><<<dim3(8,2,8), 128, GSMEM_BYTES>>>(gsc, gKV + 1024, nullptr, nullptr,
        gorep, nullptr, NQ, D_MODEL, SEQ_S, SEQ_S, 2048,
        256LL*4096, 4096LL*2048, 256LL*1024, 1.0f, 0, 0);

    // 13. cross out-proj + residual -> [NQ,B,D]
    gemm_tc<0,0,0><<<dim3(8,16,1), 128, GSMEM_BYTES>>>(gorep, wo, bo, gq1,
        gq2, nullptr, M_TOK, D_MODEL, D_MODEL, D_MODEL, D_MODEL, 0, 0, 0, 1.0f, 256, 8);

    // 14. ln3
    ln_k<<<M_TOK, 256>>>(gq2, ln3_g, ln3_b, gx);

    // 15. FFN1 + GELU
    gemm_tc<0,1,0><<<dim3(32,16,1), 128, GSMEM_BYTES>>>(gx, w1, b1, nullptr,
        gh, nullptr, M_TOK, FF_DIM, D_MODEL, D_MODEL, D_MODEL, 0, 0, 0, 1.0f, 0, 0);

    // 16. FFN2 + residual -> out_q, dual-store gathered copy -> gqm [B,NQ,D]
    gemm_tc<0,0,0><<<dim3(8,16,1), 128, GSMEM_BYTES>>>(gh, w2, b2, gq2,
        out_q, gqm, M_TOK, D_MODEL, FF_DIM, FF_DIM, FF_DIM, 0, 0, 0, 1.0f, 0, 0);

    // 17. mask logits + sigmoid -> out_m
    gemm_tc<0,2,0><<<dim3(32,16,1), 128, GSMEM_BYTES>>>(gqm, mask_w, mask_b, nullptr,
        out_m, nullptr, M_TOK, SEQ_S, D_MODEL, D_MODEL, D_MODEL, 0, 0, 0, 1.0f, 0, 0);
}

// round 12
// speedup vs baseline: 1.2663x; 1.0074x over previous
#include <cuda_runtime.h>
#include <math.h>

// ---------------------------------------------------------------------------
// Problem constants
// ---------------------------------------------------------------------------
#define D_MODEL 1024
#define NHEAD   8
#define HDIM    128
#define NQ      256
#define BATCH   8
#define SEQ_S   4096
#define FF_DIM  4096
#define M_TOK   (NQ*BATCH)       // 2048
#define M_MEM   (SEQ_S*BATCH)    // 32768

// ---------------------------------------------------------------------------
// Scratch (offsets in floats)
// ---------------------------------------------------------------------------
#define OFF_X      0LL                       // ln out [2048,1024]
#define OFF_PACK   2097152LL                 // q,k,v packed [3][64][256][128]
#define OFF_SCORES 8388608LL                 // fp32 scores (8.39M)
#define OFF_OREP   16777216LL                // attn-out repacked [2048,1024]
#define OFF_Q1     18874368LL
#define OFF_QC     20971520LL                // cross Q [8,256,1024]
#define OFF_KV     23068672LL                // fused K|V [8][4096][2048]
#define OFF_Q2     90177536LL
#define OFF_H      92274688LL                // FFN hidden [2048,4096]
#define OFF_QM     100663296LL               // query gathered [B,NQ,D]
#define OFF_WKV    102760448LL               // concat wk|wv [2048,1024]
#define OFF_BKV    104857600LL               // concat bias [2048]
#define SCRATCH_TOTAL 104859648LL

__device__ float g_scratch[SCRATCH_TOTAL];

// ---------------------------------------------------------------------------
// Helpers
// ---------------------------------------------------------------------------
__device__ __forceinline__ float gelu_exact(float x) {
    return 0.5f * x * (1.0f + erff(x * 0.70710678118654752f));
}
__device__ __forceinline__ float f2tf_f(float x) {
    unsigned u;
    asm("cvt.rna.tf32.f32 %0, %1;" : "=r"(u) : "f"(x));
    return __uint_as_float(u);
}

// ---------------------------------------------------------------------------
// tf32 tensor-core batched GEMM, 4-stage cp.async pipeline.
// 128 threads, 4 warps. CTA tile MTILE x 128 x 16.
//   MTILE=128: warp tile 64x64 (2x2 warp grid), acc[4][8][4]
//   MTILE=64 : warp tile 32x64 (2x2 warp grid), acc[2][8][4]
//   C = act( alpha * A @ op(B) + bias + resid )
//   BLAYOUT 0: B is [N,K] (A@B^T). BLAYOUT 1: B is [K,N].
//   ACT: 0 none, 1 gelu, 2 sigmoid.
//   PK: 0 normal (permP/permQ remap; DUAL -> extra gathered store to C2)
//       1 QKV head-pack epilogue    2 self-AV o-pack epilogue
//   RNDC: round C store to tf32 (rna) — for outputs feeding another GEMM.
// Dynamic smem: GSTAGES * (MTILE*20 + 2560) floats.
// ---------------------------------------------------------------------------
#define GSTAGES 4
#define GS_BYTES(MT_) (GSTAGES * ((MT_)*20 + 2560) * 4)

template<int BLAYOUT, int ACT, int PK, int MTILE, int RNDC, int DUAL>
__global__ void __launch_bounds__(128, 2)
gemm_tc(const float* __restrict__ A, const float* __restrict__ B,
        const float* __restrict__ bias, const float* __restrict__ resid,
        float* __restrict__ C, float* __restrict__ C2,
        int M, int N, int K, int lda, int ldb,
        long long bA, long long bB, long long bC,
        float alpha, int permP, int permQ)
{
    constexpr int MT   = MTILE / 32;        // m-subtiles per warp; also A chunks
    constexpr int ASTR = MTILE * 20;        // A stage stride (floats)
    extern __shared__ float smemf[];
    float* As = smemf;
    float* Bs = smemf + GSTAGES * ASTR;

    const int z  = blockIdx.z;
    const float* Ab = A + (long long)z * bA;
    const float* Bb = B + (long long)z * bB;
    const int m0 = blockIdx.y * MTILE;
    const int n0 = blockIdx.x * 128;

    const int tid  = threadIdx.x;
    const int lane = tid & 31;
    const int warp = tid >> 5;
    const int warpM = warp >> 1;            // 0..1
    const int warpN = warp & 1;             // 0..1
    const int lr = lane >> 2;               // 0..7
    const int lc = lane & 3;                // 0..3

    const int a_r0 = tid >> 2;              // 0..31 (+32*i)
    const int a_kq = (tid & 3) * 4;
    const float* Aptr = Ab + (long long)(m0 + a_r0) * lda + a_kq;

    const float* Bptr;
    int b1_k0 = 0, b1_nq = 0;
    if (BLAYOUT == 0) {
        Bptr = Bb + (long long)(n0 + a_r0) * ldb + a_kq;
    } else {
        b1_k0 = tid >> 5;
        b1_nq = (tid & 31) * 4;
        Bptr = Bb + (long long)b1_k0 * ldb + n0 + b1_nq;
    }

    const unsigned sAu = (unsigned)__cvta_generic_to_shared(As);
    const unsigned sBu = (unsigned)__cvta_generic_to_shared(Bs);
    const unsigned dA0 = sAu + (unsigned)(a_r0 * 20 + a_kq) * 4u;
    const unsigned dB0 = (BLAYOUT == 0)
        ? sBu + (unsigned)(a_r0 * 20 + a_kq) * 4u
        : sBu + (unsigned)(b1_k0 * 136 + b1_nq) * 4u;

    const int nkt = K >> 4;

    auto issue = [&](int kt, int slot) {
        const long long ka = (long long)kt * 16;
        const unsigned soA = (unsigned)slot * (unsigned)ASTR * 4u;
        const unsigned soB = (unsigned)slot * 2560u * 4u;
        #pragma unroll
        for (int i = 0; i < MT; i++) {
            const float* g = Aptr + (long long)i * 32 * lda + ka;
            unsigned d = dA0 + soA + (unsigned)(i * 32 * 20) * 4u;
            asm volatile("cp.async.cg.shared.global [%0], [%1], 16;\n" :: "r"(d), "l"(g));
        }
        if (BLAYOUT == 0) {
            #pragma unroll
            for (int i = 0; i < 4; i++) {
                const float* g = Bptr + (long long)i * 32 * ldb + ka;
                unsigned d = dB0 + soB + (unsigned)(i * 32 * 20) * 4u;
                asm volatile("cp.async.cg.shared.global [%0], [%1], 16;\n" :: "r"(d), "l"(g));
            }
        } else {
            #pragma unroll
            for (int i = 0; i < 4; i++) {
                const float* g = Bptr + (ka + (long long)i * 4) * ldb;
                unsigned d = dB0 + soB + (unsigned)(i * 4 * 136) * 4u;
                asm volatile("cp.async.cg.shared.global [%0], [%1], 16;\n" :: "r"(d), "l"(g));
            }
        }
        asm volatile("cp.async.commit_group;\n");
    };

    float acc[MT][8][4];
    #pragma unroll
    for (int a = 0; a < MT; a++)
        #pragma unroll
        for (int b = 0; b < 8; b++)
            #pragma unroll
            for (int c = 0; c < 4; c++) acc[a][b][c] = 0.f;

    #pragma unroll
    for (int s = 0; s < GSTAGES - 1; s++) {
        if (s < nkt) issue(s, s);
        else asm volatile("cp.async.commit_group;\n");
    }

    for (int kt = 0; kt < nkt; kt++) {
        asm volatile("cp.async.wait_group %0;\n" :: "n"(GSTAGES - 2));
        __syncthreads();

        const int nx = kt + GSTAGES - 1;
        if (nx < nkt) issue(nx, nx & (GSTAGES - 1));
        else asm volatile("cp.async.commit_group;\n");

        const float* Asb = As + (kt & (GSTAGES - 1)) * ASTR;
        const float* Bsb = Bs + (kt & (GSTAGES - 1)) * 2560;

        #pragma unroll
        for (int k8 = 0; k8 < 2; k8++) {
            const int c = k8 * 8 + lc;
            unsigned bf[8][2];
            #pragma unroll
            for (int nt = 0; nt < 8; nt++) {
                if (BLAYOUT == 0) {
                    const int nn = warpN*64 + nt*8 + lr;
                    bf[nt][0] = __float_as_uint(Bsb[nn*20 + c]);
                    bf[nt][1] = __float_as_uint(Bsb[nn*20 + c + 4]);
                } else {
                    const int kk = k8*8 + lc;
                    const int nn = warpN*64 + nt*8 + lr;
                    bf[nt][0] = __float_as_uint(Bsb[kk*136 + nn]);
                    bf[nt][1] = __float_as_uint(Bsb[(kk+4)*136 + nn]);
                }
            }
            #pragma unroll
            for (int mt = 0; mt < MT; mt++) {
                const int r = warpM*(MTILE/2) + mt*16 + lr;
                unsigned a0 = __float_as_uint(Asb[r*20 + c]);
                unsigned a1 = __float_as_uint(Asb[(r+8)*20 + c]);
                unsigned a2 = __float_as_uint(Asb[r*20 + c + 4]);
                unsigned a3 = __float_as_uint(Asb[(r+8)*20 + c + 4]);
                #pragma unroll
                for (int nt = 0; nt < 8; nt++) {
                    asm volatile(
                        "mma.sync.aligned.m16n8k8.row.col.f32.tf32.tf32.f32 "
                        "{%0,%1,%2,%3}, {%4,%5,%6,%7}, {%8,%9}, {%0,%1,%2,%3};"
                        : "+f"(acc[mt][nt][0]), "+f"(acc[mt][nt][1]),
                          "+f"(acc[mt][nt][2]), "+f"(acc[mt][nt][3])
                        : "r"(a0), "r"(a1), "r"(a2), "r"(a3),
                          "r"(bf[nt][0]), "r"(bf[nt][1]));
                }
            }
        }
    }

    // ---- epilogue ----
    #pragma unroll
    for (int mt = 0; mt < MT; mt++) {
        #pragma unroll
        for (int h = 0; h < 2; h++) {
            const int gm = m0 + warpM*(MTILE/2) + mt*16 + lr + h*8;
            #pragma unroll
            for (int nt = 0; nt < 8; nt++) {
                const int gn = n0 + warpN*64 + nt*8 + 2*lc;
                float v0 = acc[mt][nt][2*h+0] * alpha;
                float v1 = acc[mt][nt][2*h+1] * alpha;
                if (PK != 2) {
                    if (bias) { v0 += bias[gn]; v1 += bias[gn+1]; }
                }
                if (PK == 1) {
                    const int b = gm & 7, l = gm >> 3;
                    const int sec = gn >> 10, hh = (gn >> 7) & 7, d = gn & 127;
                    const long long idx = (long long)sec * 2097152LL
                        + ((long long)(b*8 + hh) * 256 + l) * 128 + d;
                    if (RNDC) { v0 = f2tf_f(v0); v1 = f2tf_f(v1); }
                    float2 o; o.x = v0; o.y = v1;
                    *(float2*)(&C[idx]) = o;
                } else if (PK == 2) {
                    const int b = z >> 3, hh = z & 7;
                    const long long idx = ((long long)(gm*8 + b)) * 1024 + hh*128 + gn;
                    if (RNDC) { v0 = f2tf_f(v0); v1 = f2tf_f(v1); }
                    float2 o; o.x = v0; o.y = v1;
                    *(float2*)(&C[idx]) = o;
                } else {
                    const int rm = (permP > 0) ? ((gm % permP) * permQ + gm / permP) : gm;
                    const long long base = (long long)z * bC + (long long)rm * N;
                    if (resid) { v0 += resid[base + gn]; v1 += resid[base + gn + 1]; }
                    if (ACT == 1) { v0 = gelu_exact(v0); v1 = gelu_exact(v1); }
                    else if (ACT == 2) {
                        v0 = 1.0f / (1.0f + expf(-v0));
                        v1 = 1.0f / (1.0f + expf(-v1));
                    }
                    float2 o;
                    if (RNDC) { o.x = f2tf_f(v0); o.y = f2tf_f(v1); }
                    else      { o.x = v0; o.y = v1; }
                    *(float2*)(&C[base + gn]) = o;
                    if (DUAL) {
                        const int r2 = (gm & 7) * 256 + (gm >> 3);
                        float2 o2; o2.x = f2tf_f(v0); o2.y = f2tf_f(v1);
                        *(float2*)(&C2[(long long)r2 * N + gn]) = o2;
                    }
                }
            }
        }
    }
}

// ---------------------------------------------------------------------------
// Concat wk|wv weights + biases into fused buffers (tf32-rounded, free)
// ---------------------------------------------------------------------------
__global__ void concat_kv_k(const float* __restrict__ wk, const float* __restrict__ wv,
                            const float* __restrict__ bk, const float* __restrict__ bv,
                            float* __restrict__ w, float* __restrict__ b)
{
    const int i = blockIdx.x * 256 + threadIdx.x;
    if (i < 524288) {
        float4 v = (i < 262144) ? ((const float4*)wk)[i] : ((const float4*)wv)[i - 262144];
        v.x = f2tf_f(v.x); v.y = f2tf_f(v.y); v.z = f2tf_f(v.z); v.w = f2tf_f(v.w);
        ((float4*)w)[i] = v;
    } else if (i < 524800) {
        const int j = i - 524288;
        float4 v = (j < 256) ? ((const float4*)bk)[j] : ((const float4*)bv)[j - 256];
        ((float4*)b)[j] = v;
    }
}

// ---------------------------------------------------------------------------
// LayerNorm over D=1024 (output tf32-rounded; always feeds a GEMM A operand)
// ---------------------------------------------------------------------------
__global__ void ln_k(const float* __restrict__ x, const float* __restrict__ g,
                     const float* __restrict__ b, float* __restrict__ y)
{
    const long long row = blockIdx.x;
    const float* xr = x + row * D_MODEL;
    float* yr = y + row * D_MODEL;
    const int t = threadIdx.x;

    float v[4], s = 0.f, s2 = 0.f;
    #pragma unroll
    for (int i = 0; i < 4; i++) {
        v[i] = xr[t + i * 256];
        s  += v[i];
        s2 += v[i] * v[i];
    }
    #pragma unroll
    for (int o = 16; o > 0; o >>= 1) {
        s  += __shfl_xor_sync(0xFFFFFFFFu, s,  o);
        s2 += __shfl_xor_sync(0xFFFFFFFFu, s2, o);
    }
    __shared__ float shs[8], shs2[8];
    if ((t & 31) == 0) { shs[t >> 5] = s; shs2[t >> 5] = s2; }
    __syncthreads();
    float S = 0.f, S2 = 0.f;
    #pragma unroll
    for (int w = 0; w < 8; w++) { S += shs[w]; S2 += shs2[w]; }

    const float mean = S * (1.0f / D_MODEL);
    const float var  = S2 * (1.0f / D_MODEL) - mean * mean;
    const float inv  = rsqrtf(var + 1e-5f);
    #pragma unroll
    for (int i = 0; i < 4; i++) {
        const int c = t + i * 256;
        yr[c] = f2tf_f((v[i] - mean) * inv * g[c] + b[c]);
    }
}

// ---------------------------------------------------------------------------
// Row softmax in-place fp32 (optionally + log(prev_mask + 1e-6)); tf32 out
// ---------------------------------------------------------------------------
__global__ void softmax_k(float* __restrict__ s, const float* __restrict__ pm, int cols)
{
    const long long row = blockIdx.x;
    float* r = s + row * cols;
    const float* pmr = pm ? pm + row * cols : nullptr;
    const int t = threadIdx.x;
    const int nc = cols >> 8;

    float lv[16];
    float mx = -1e30f;
    for (int i = 0; i < nc; i++) {
        float v = r[t + (i << 8)];
        if (pmr) v += logf(pmr[t + (i << 8)] + 1e-6f);
        lv[i] = v;
        mx = fmaxf(mx, v);
    }
    #pragma unroll
    for (int o = 16; o > 0; o >>= 1)
        mx = fmaxf(mx, __shfl_xor_sync(0xFFFFFFFFu, mx, o));
    __shared__ float shm[8], shsum[8];
    if ((t & 31) == 0) shm[t >> 5] = mx;
    __syncthreads();
    float MX = shm[0];
    #pragma unroll
    for (int w = 1; w < 8; w++) MX = fmaxf(MX, shm[w]);

    float sum = 0.f;
    for (int i = 0; i < nc; i++) {
        const float e = expf(lv[i] - MX);
        lv[i] = e;
        sum += e;
    }
    #pragma unroll
    for (int o = 16; o > 0; o >>= 1)
        sum += __shfl_xor_sync(0xFFFFFFFFu, sum, o);
    if ((t & 31) == 0) shsum[t >> 5] = sum;
    __syncthreads();
    float SUM = 0.f;
    #pragma unroll
    for (int w = 0; w < 8; w++) SUM += shsum[w];

    const float inv = 1.0f / SUM;
    for (int i = 0; i < nc; i++) r[t + (i << 8)] = f2tf_f(lv[i] * inv);
}

// ---------------------------------------------------------------------------
// kernel_launch
// ---------------------------------------------------------------------------
extern "C" void kernel_launch(void* const* d_in, const int* in_sizes, int n_in,
                              void* d_out, int out_size)
{
    const float* query    = (const float*)d_in[0];
    const float* memory   = (const float*)d_in[1];
    const float* prevmask = (const float*)d_in[2];
    const float* sa_in_w  = (const float*)d_in[5];
    const float* sa_in_b  = (const float*)d_in[6];
    const float* sa_out_w = (const float*)d_in[7];
    const float* sa_out_b = (const float*)d_in[8];
    const float* ln1_g = (const float*)d_in[9];
    const float* ln1_b = (const float*)d_in[10];
    const float* ln2_g = (const float*)d_in[11];
    const float* ln2_b = (const float*)d_in[12];
    const float* ln3_g = (const float*)d_in[13];
    const float* ln3_b = (const float*)d_in[14];
    const float* wq = (const float*)d_in[15];
    const float* bq = (const float*)d_in[16];
    const float* wk = (const float*)d_in[17];
    const float* bk = (const float*)d_in[18];
    const float* wv = (const float*)d_in[19];
    const float* bv = (const float*)d_in[20];
    const float* wo = (const float*)d_in[21];
    const float* bo = (const float*)d_in[22];
    const float* w1 = (const float*)d_in[23];
    const float* b1 = (const float*)d_in[24];
    const float* w2 = (const float*)d_in[25];
    const float* b2 = (const float*)d_in[26];
    const float* mask_w = (const float*)d_in[27];
    const float* mask_b = (const float*)d_in[28];

    float* scr = nullptr;
    cudaGetSymbolAddress((void**)&scr, g_scratch);

    float* gx    = scr + OFF_X;
    float* gq    = scr + OFF_PACK;
    float* gk    = scr + OFF_PACK + 2097152LL;
    float* gv    = scr + OFF_PACK + 4194304LL;
    float* gsc   = scr + OFF_SCORES;
    float* gorep = scr + OFF_OREP;
    float* gq1   = scr + OFF_Q1;
    float* gQc   = scr + OFF_QC;
    float* gKV   = scr + OFF_KV;
    float* gq2   = scr + OFF_Q2;
    float* gh    = scr + OFF_H;
    float* gqm   = scr + OFF_QM;
    float* gwkv  = scr + OFF_WKV;
    float* gbkv  = scr + OFF_BKV;

    float* out_q = (float*)d_out;
    float* out_m = out_q + (long long)M_TOK * D_MODEL;

    const float inv_sqrt_hd = 0.088388347648318447f;
    const float inv_sqrt_d  = 0.03125f;

    // set dynamic smem attr per instantiation
    cudaFuncSetAttribute(gemm_tc<0,0,1,128,1,0>, cudaFuncAttributeMaxDynamicSharedMemorySize, GS_BYTES(128));
    cudaFuncSetAttribute(gemm_tc<0,0,0,128,0,0>, cudaFuncAttributeMaxDynamicSharedMemorySize, GS_BYTES(128));
    cudaFuncSetAttribute(gemm_tc<0,0,0,128,1,0>, cudaFuncAttributeMaxDynamicSharedMemorySize, GS_BYTES(128));
    cudaFuncSetAttribute(gemm_tc<0,1,0,128,1,0>, cudaFuncAttributeMaxDynamicSharedMemorySize, GS_BYTES(128));
    cudaFuncSetAttribute(gemm_tc<0,2,0,128,0,0>, cudaFuncAttributeMaxDynamicSharedMemorySize, GS_BYTES(128));
    cudaFuncSetAttribute(gemm_tc<1,0,2,64,1,0>,  cudaFuncAttributeMaxDynamicSharedMemorySize, GS_BYTES(64));
    cudaFuncSetAttribute(gemm_tc<0,0,0,64,0,0>,  cudaFuncAttributeMaxDynamicSharedMemorySize, GS_BYTES(64));
    cudaFuncSetAttribute(gemm_tc<0,0,0,64,1,0>,  cudaFuncAttributeMaxDynamicSharedMemorySize, GS_BYTES(64));
    cudaFuncSetAttribute(gemm_tc<1,0,0,64,1,0>,  cudaFuncAttributeMaxDynamicSharedMemorySize, GS_BYTES(64));
    cudaFuncSetAttribute(gemm_tc<0,0,0,64,0,1>,  cudaFuncAttributeMaxDynamicSharedMemorySize, GS_BYTES(64));

    // 0. concat + round wk|wv
    concat_kv_k<<<2051, 256>>>(wk, wv, bk, bv, gwkv, gbkv);

    // 1. ln1(query) (rounds)
    ln_k<<<M_TOK, 256>>>(query, ln1_g, ln1_b, gx);

    // 2. QKV projection + head-pack (rounds)
    gemm_tc<0,0,1,128,1,0><<<dim3(24,16,1), 128, GS_BYTES(128)>>>(gx, sa_in_w, sa_in_b, nullptr,
        gq, nullptr, M_TOK, 3*D_MODEL, D_MODEL, D_MODEL, D_MODEL, 0, 0, 0, 1.0f, 0, 0);

    // 3. self-attn scores (batched 64)
    gemm_tc<0,0,0,128,0,0><<<dim3(2,2,64), 128, GS_BYTES(128)>>>(gq, gk, nullptr, nullptr,
        gsc, nullptr, NQ, NQ, HDIM, HDIM, HDIM, 256LL*128, 256LL*128, 256LL*256,
        inv_sqrt_hd, 0, 0);

    // 4. softmax (rounds)
    softmax_k<<<64*256, 256>>>(gsc, nullptr, 256);

    // 5. o = attn @ v + o-pack (rounds), MTILE=64 -> better fill
    gemm_tc<1,0,2,64,1,0><<<dim3(1,4,64), 128, GS_BYTES(64)>>>(gsc, gv, nullptr, nullptr,
        gorep, nullptr, NQ, HDIM, NQ, NQ, HDIM, 256LL*256, 256LL*128, 0, 1.0f, 0, 0);

    // 6. self out-proj + residual (fp32 exact out), MTILE=64
    gemm_tc<0,0,0,64,0,0><<<dim3(8,32,1), 128, GS_BYTES(64)>>>(gorep, sa_out_w, sa_out_b, query,
        gq1, nullptr, M_TOK, D_MODEL, D_MODEL, D_MODEL, D_MODEL, 0, 0, 0, 1.0f, 0, 0);

    // 7. ln2 (rounds)
    ln_k<<<M_TOK, 256>>>(gq1, ln2_g, ln2_b, gx);

    // 8. Q proj -> [B,NQ,D] (rounds), MTILE=64
    gemm_tc<0,0,0,64,1,0><<<dim3(8,32,1), 128, GS_BYTES(64)>>>(gx, wq, bq, nullptr,
        gQc, nullptr, M_TOK, D_MODEL, D_MODEL, D_MODEL, D_MODEL, 0, 0, 0, 1.0f, 8, 256);

    // 9. fused K|V projection -> gKV [8][4096][2048] (rounds)
    gemm_tc<0,0,0,128,1,0><<<dim3(16,256,1), 128, GS_BYTES(128)>>>(memory, gwkv, gbkv, nullptr,
        gKV, nullptr, M_MEM, 2048, D_MODEL, D_MODEL, D_MODEL, 0, 0, 0, 1.0f, 8, 4096);

    // 10. cross scores: Q @ K'^T
    gemm_tc<0,0,0,128,0,0><<<dim3(32,2,8), 128, GS_BYTES(128)>>>(gQc, gKV, nullptr, nullptr,
        gsc, nullptr, NQ, SEQ_S, D_MODEL, D_MODEL, 2048,
        256LL*1024, 4096LL*2048, 256LL*4096, inv_sqrt_d, 0, 0);

    // 11. softmax + log(prev_mask) (rounds)
    softmax_k<<<BATCH*NQ, 256>>>(gsc, prevmask, SEQ_S);

    // 12. attn_out = attn @ V' (rounds), MTILE=64
    gemm_tc<1,0,0,64,1,0><<<dim3(8,4,8), 128, GS_BYTES(64)>>>(gsc, gKV + 1024, nullptr, nullptr,
        gorep, nullptr, NQ, D_MODEL, SEQ_S, SEQ_S, 2048,
        256LL*4096, 4096LL*2048, 256LL*1024, 1.0f, 0, 0);

    // 13. cross out-proj + residual -> [NQ,B,D] (fp32 exact), MTILE=64
    gemm_tc<0,0,0,64,0,0><<<dim3(8,32,1), 128, GS_BYTES(64)>>>(gorep, wo, bo, gq1,
        gq2, nullptr, M_TOK, D_MODEL, D_MODEL, D_MODEL, D_MODEL, 0, 0, 0, 1.0f, 256, 8);

    // 14. ln3 (rounds)
    ln_k<<<M_TOK, 256>>>(gq2, ln3_g, ln3_b, gx);

    // 15. FFN1 + GELU (rounds)
    gemm_tc<0,1,0,128,1,0><<<dim3(32,16,1), 128, GS_BYTES(128)>>>(gx, w1, b1, nullptr,
        gh, nullptr, M_TOK, FF_DIM, D_MODEL, D_MODEL, D_MODEL, 0, 0, 0, 1.0f, 0, 0);

    // 16. FFN2 + residual -> out_q exact; dual rounded gather -> gqm, MTILE=64
    gemm_tc<0,0,0,64,0,1><<<dim3(8,32,1), 128, GS_BYTES(64)>>>(gh, w2, b2, gq2,
        out_q, gqm, M_TOK, D_MODEL, FF_DIM, FF_DIM, FF_DIM, 0, 0, 0, 1.0f, 0, 0);

    // 17. mask logits + sigmoid -> out_m
    gemm_tc<0,2,0,128,0,0><<<dim3(32,16,1), 128, GS_BYTES(128)>>>(gqm, mask_w, mask_b, nullptr,
        out_m, nullptr, M_TOK, SEQ_S, D_MODEL, D_MODEL, D_MODEL, 0, 0, 0, 1.0f, 0, 0);
}

// round 13
// speedup vs baseline: 1.4421x; 1.1388x over previous
#include <cuda_runtime.h>
#include <math.h>

// ---------------------------------------------------------------------------
// Problem constants
// ---------------------------------------------------------------------------
#define D_MODEL 1024
#define NHEAD   8
#define HDIM    128
#define NQ      256
#define BATCH   8
#define SEQ_S   4096
#define FF_DIM  4096
#define M_TOK   (NQ*BATCH)       // 2048
#define M_MEM   (SEQ_S*BATCH)    // 32768

// ---------------------------------------------------------------------------
// Scratch (offsets in floats)
// ---------------------------------------------------------------------------
#define OFF_X      0LL                       // ln out [2048,1024]
#define OFF_PACK   2097152LL                 // q,k,v packed [3][64][256][128]
#define OFF_SCORES 8388608LL                 // scores (max 8*256*4096)
#define OFF_OREP   16777216LL                // repacked attn-out / AM [2048,1024]
#define OFF_Q1     18874368LL
#define OFF_QC     20971520LL                // cross Q [8,256,1024] (b-major)
#define OFF_QP     23068672LL                // Q@wk / cross attn_out [2048,1024]
#define OFF_Q2     25165824LL
#define OFF_H      27262976LL                // FFN hidden [2048,4096]
#define OFF_QM     35651584LL                // query gathered [B,NQ,D]
#define OFF_WKR    37748736LL                // rounded wk [1024,1024]
#define SCRATCH_TOTAL 38797312LL

__device__ float g_scratch[SCRATCH_TOTAL];

// ---------------------------------------------------------------------------
// Helpers
// ---------------------------------------------------------------------------
__device__ __forceinline__ float gelu_exact(float x) {
    return 0.5f * x * (1.0f + erff(x * 0.70710678118654752f));
}
__device__ __forceinline__ float f2tf_f(float x) {
    unsigned u;
    asm("cvt.rna.tf32.f32 %0, %1;" : "=r"(u) : "f"(x));
    return __uint_as_float(u);
}

// ---------------------------------------------------------------------------
// tf32 tensor-core batched GEMM, 4-stage cp.async pipeline.
// 128 threads, 4 warps. CTA tile MTILE x 128 x 16.
//   C = act( alpha * A @ op(B) + bias + resid )
//   BLAYOUT 0: B is [N,K] (A@B^T). BLAYOUT 1: B is [K,N].
//   ACT: 0 none, 1 gelu, 2 sigmoid.
//   PK: 0 normal (permP/permQ remap; DUAL -> extra rounded gather to C2)
//       1 QKV head-pack epilogue    2 self-AV o-pack epilogue
//   RNDC: round C store to tf32 (rna) — for outputs feeding another GEMM.
// Dynamic smem: GSTAGES * (MTILE*20 + 2560) floats.
// ---------------------------------------------------------------------------
#define GSTAGES 4
#define GS_BYTES(MT_) (GSTAGES * ((MT_)*20 + 2560) * 4)

template<int BLAYOUT, int ACT, int PK, int MTILE, int RNDC, int DUAL>
__global__ void __launch_bounds__(128, 2)
gemm_tc(const float* __restrict__ A, const float* __restrict__ B,
        const float* __restrict__ bias, const float* __restrict__ resid,
        float* __restrict__ C, float* __restrict__ C2,
        int M, int N, int K, int lda, int ldb,
        long long bA, long long bB, long long bC,
        float alpha, int permP, int permQ)
{
    constexpr int MT   = MTILE / 32;
    constexpr int ASTR = MTILE * 20;
    extern __shared__ float smemf[];
    float* As = smemf;
    float* Bs = smemf + GSTAGES * ASTR;

    const int z  = blockIdx.z;
    const float* Ab = A + (long long)z * bA;
    const float* Bb = B + (long long)z * bB;
    const int m0 = blockIdx.y * MTILE;
    const int n0 = blockIdx.x * 128;

    const int tid  = threadIdx.x;
    const int lane = tid & 31;
    const int warp = tid >> 5;
    const int warpM = warp >> 1;
    const int warpN = warp & 1;
    const int lr = lane >> 2;
    const int lc = lane & 3;

    const int a_r0 = tid >> 2;
    const int a_kq = (tid & 3) * 4;
    const float* Aptr = Ab + (long long)(m0 + a_r0) * lda + a_kq;

    const float* Bptr;
    int b1_k0 = 0, b1_nq = 0;
    if (BLAYOUT == 0) {
        Bptr = Bb + (long long)(n0 + a_r0) * ldb + a_kq;
    } else {
        b1_k0 = tid >> 5;
        b1_nq = (tid & 31) * 4;
        Bptr = Bb + (long long)b1_k0 * ldb + n0 + b1_nq;
    }

    const unsigned sAu = (unsigned)__cvta_generic_to_shared(As);
    const unsigned sBu = (unsigned)__cvta_generic_to_shared(Bs);
    const unsigned dA0 = sAu + (unsigned)(a_r0 * 20 + a_kq) * 4u;
    const unsigned dB0 = (BLAYOUT == 0)
        ? sBu + (unsigned)(a_r0 * 20 + a_kq) * 4u
        : sBu + (unsigned)(b1_k0 * 136 + b1_nq) * 4u;

    const int nkt = K >> 4;

    auto issue = [&](int kt, int slot) {
        const long long ka = (long long)kt * 16;
        const unsigned soA = (unsigned)slot * (unsigned)ASTR * 4u;
        const unsigned soB = (unsigned)slot * 2560u * 4u;
        #pragma unroll
        for (int i = 0; i < MT; i++) {
            const float* g = Aptr + (long long)i * 32 * lda + ka;
            unsigned d = dA0 + soA + (unsigned)(i * 32 * 20) * 4u;
            asm volatile("cp.async.cg.shared.global [%0], [%1], 16;\n" :: "r"(d), "l"(g));
        }
        if (BLAYOUT == 0) {
            #pragma unroll
            for (int i = 0; i < 4; i++) {
                const float* g = Bptr + (long long)i * 32 * ldb + ka;
                unsigned d = dB0 + soB + (unsigned)(i * 32 * 20) * 4u;
                asm volatile("cp.async.cg.shared.global [%0], [%1], 16;\n" :: "r"(d), "l"(g));
            }
        } else {
            #pragma unroll
            for (int i = 0; i < 4; i++) {
                const float* g = Bptr + (ka + (long long)i * 4) * ldb;
                unsigned d = dB0 + soB + (unsigned)(i * 4 * 136) * 4u;
                asm volatile("cp.async.cg.shared.global [%0], [%1], 16;\n" :: "r"(d), "l"(g));
            }
        }
        asm volatile("cp.async.commit_group;\n");
    };

    float acc[MT][8][4];
    #pragma unroll
    for (int a = 0; a < MT; a++)
        #pragma unroll
        for (int b = 0; b < 8; b++)
            #pragma unroll
            for (int c = 0; c < 4; c++) acc[a][b][c] = 0.f;

    #pragma unroll
    for (int s = 0; s < GSTAGES - 1; s++) {
        if (s < nkt) issue(s, s);
        else asm volatile("cp.async.commit_group;\n");
    }

    for (int kt = 0; kt < nkt; kt++) {
        asm volatile("cp.async.wait_group %0;\n" :: "n"(GSTAGES - 2));
        __syncthreads();

        const int nx = kt + GSTAGES - 1;
        if (nx < nkt) issue(nx, nx & (GSTAGES - 1));
        else asm volatile("cp.async.commit_group;\n");

        const float* Asb = As + (kt & (GSTAGES - 1)) * ASTR;
        const float* Bsb = Bs + (kt & (GSTAGES - 1)) * 2560;

        #pragma unroll
        for (int k8 = 0; k8 < 2; k8++) {
            const int c = k8 * 8 + lc;
            unsigned bf[8][2];
            #pragma unroll
            for (int nt = 0; nt < 8; nt++) {
                if (BLAYOUT == 0) {
                    const int nn = warpN*64 + nt*8 + lr;
                    bf[nt][0] = __float_as_uint(Bsb[nn*20 + c]);
                    bf[nt][1] = __float_as_uint(Bsb[nn*20 + c + 4]);
                } else {
                    const int kk = k8*8 + lc;
                    const int nn = warpN*64 + nt*8 + lr;
                    bf[nt][0] = __float_as_uint(Bsb[kk*136 + nn]);
                    bf[nt][1] = __float_as_uint(Bsb[(kk+4)*136 + nn]);
                }
            }
            #pragma unroll
            for (int mt = 0; mt < MT; mt++) {
                const int r = warpM*(MTILE/2) + mt*16 + lr;
                unsigned a0 = __float_as_uint(Asb[r*20 + c]);
                unsigned a1 = __float_as_uint(Asb[(r+8)*20 + c]);
                unsigned a2 = __float_as_uint(Asb[r*20 + c + 4]);
                unsigned a3 = __float_as_uint(Asb[(r+8)*20 + c + 4]);
                #pragma unroll
                for (int nt = 0; nt < 8; nt++) {
                    asm volatile(
                        "mma.sync.aligned.m16n8k8.row.col.f32.tf32.tf32.f32 "
                        "{%0,%1,%2,%3}, {%4,%5,%6,%7}, {%8,%9}, {%0,%1,%2,%3};"
                        : "+f"(acc[mt][nt][0]), "+f"(acc[mt][nt][1]),
                          "+f"(acc[mt][nt][2]), "+f"(acc[mt][nt][3])
                        : "r"(a0), "r"(a1), "r"(a2), "r"(a3),
                          "r"(bf[nt][0]), "r"(bf[nt][1]));
                }
            }
        }
    }

    // ---- epilogue ----
    #pragma unroll
    for (int mt = 0; mt < MT; mt++) {
        #pragma unroll
        for (int h = 0; h < 2; h++) {
            const int gm = m0 + warpM*(MTILE/2) + mt*16 + lr + h*8;
            #pragma unroll
            for (int nt = 0; nt < 8; nt++) {
                const int gn = n0 + warpN*64 + nt*8 + 2*lc;
                float v0 = acc[mt][nt][2*h+0] * alpha;
                float v1 = acc[mt][nt][2*h+1] * alpha;
                if (PK != 2) {
                    if (bias) { v0 += bias[gn]; v1 += bias[gn+1]; }
                }
                if (PK == 1) {
                    const int b = gm & 7, l = gm >> 3;
                    const int sec = gn >> 10, hh = (gn >> 7) & 7, d = gn & 127;
                    const long long idx = (long long)sec * 2097152LL
                        + ((long long)(b*8 + hh) * 256 + l) * 128 + d;
                    if (RNDC) { v0 = f2tf_f(v0); v1 = f2tf_f(v1); }
                    float2 o; o.x = v0; o.y = v1;
                    *(float2*)(&C[idx]) = o;
                } else if (PK == 2) {
                    const int b = z >> 3, hh = z & 7;
                    const long long idx = ((long long)(gm*8 + b)) * 1024 + hh*128 + gn;
                    if (RNDC) { v0 = f2tf_f(v0); v1 = f2tf_f(v1); }
                    float2 o; o.x = v0; o.y = v1;
                    *(float2*)(&C[idx]) = o;
                } else {
                    const int rm = (permP > 0) ? ((gm % permP) * permQ + gm / permP) : gm;
                    const long long base = (long long)z * bC + (long long)rm * N;
                    if (resid) { v0 += resid[base + gn]; v1 += resid[base + gn + 1]; }
                    if (ACT == 1) { v0 = gelu_exact(v0); v1 = gelu_exact(v1); }
                    else if (ACT == 2) {
                        v0 = 1.0f / (1.0f + expf(-v0));
                        v1 = 1.0f / (1.0f + expf(-v1));
                    }
                    float2 o;
                    if (RNDC) { o.x = f2tf_f(v0); o.y = f2tf_f(v1); }
                    else      { o.x = v0; o.y = v1; }
                    *(float2*)(&C[base + gn]) = o;
                    if (DUAL) {
                        const int r2 = (gm & 7) * 256 + (gm >> 3);
                        float2 o2; o2.x = f2tf_f(v0); o2.y = f2tf_f(v1);
                        *(float2*)(&C2[(long long)r2 * N + gn]) = o2;
                    }
                }
            }
        }
    }
}

// ---------------------------------------------------------------------------
// tf32 rounding pass (float4)
// ---------------------------------------------------------------------------
__global__ void round4_k(const float* __restrict__ in, float* __restrict__ out, int n4)
{
    const int i = blockIdx.x * 256 + threadIdx.x;
    if (i < n4) {
        float4 v = ((const float4*)in)[i];
        v.x = f2tf_f(v.x); v.y = f2tf_f(v.y);
        v.z = f2tf_f(v.z); v.w = f2tf_f(v.w);
        ((float4*)out)[i] = v;
    }
}

// ---------------------------------------------------------------------------
// LayerNorm over D=1024 (output tf32-rounded; feeds GEMM A operand)
// ---------------------------------------------------------------------------
__global__ void ln_k(const float* __restrict__ x, const float* __restrict__ g,
                     const float* __restrict__ b, float* __restrict__ y)
{
    const long long row = blockIdx.x;
    const float* xr = x + row * D_MODEL;
    float* yr = y + row * D_MODEL;
    const int t = threadIdx.x;

    float v[4], s = 0.f, s2 = 0.f;
    #pragma unroll
    for (int i = 0; i < 4; i++) {
        v[i] = xr[t + i * 256];
        s  += v[i];
        s2 += v[i] * v[i];
    }
    #pragma unroll
    for (int o = 16; o > 0; o >>= 1) {
        s  += __shfl_xor_sync(0xFFFFFFFFu, s,  o);
        s2 += __shfl_xor_sync(0xFFFFFFFFu, s2, o);
    }
    __shared__ float shs[8], shs2[8];
    if ((t & 31) == 0) { shs[t >> 5] = s; shs2[t >> 5] = s2; }
    __syncthreads();
    float S = 0.f, S2 = 0.f;
    #pragma unroll
    for (int w = 0; w < 8; w++) { S += shs[w]; S2 += shs2[w]; }

    const float mean = S * (1.0f / D_MODEL);
    const float var  = S2 * (1.0f / D_MODEL) - mean * mean;
    const float inv  = rsqrtf(var + 1e-5f);
    #pragma unroll
    for (int i = 0; i < 4; i++) {
        const int c = t + i * 256;
        yr[c] = f2tf_f((v[i] - mean) * inv * g[c] + b[c]);
    }
}

// ---------------------------------------------------------------------------
// Row softmax in-place fp32 (optionally + log(prev_mask + 1e-6)); tf32 out
// ---------------------------------------------------------------------------
__global__ void softmax_k(float* __restrict__ s, const float* __restrict__ pm, int cols)
{
    const long long row = blockIdx.x;
    float* r = s + row * cols;
    const float* pmr = pm ? pm + row * cols : nullptr;
    const int t = threadIdx.x;
    const int nc = cols >> 8;

    float lv[16];
    float mx = -1e30f;
    for (int i = 0; i < nc; i++) {
        float v = r[t + (i << 8)];
        if (pmr) v += logf(pmr[t + (i << 8)] + 1e-6f);
        lv[i] = v;
        mx = fmaxf(mx, v);
    }
    #pragma unroll
    for (int o = 16; o > 0; o >>= 1)
        mx = fmaxf(mx, __shfl_xor_sync(0xFFFFFFFFu, mx, o));
    __shared__ float shm[8], shsum[8];
    if ((t & 31) == 0) shm[t >> 5] = mx;
    __syncthreads();
    float MX = shm[0];
    #pragma unroll
    for (int w = 1; w < 8; w++) MX = fmaxf(MX, shm[w]);

    float sum = 0.f;
    for (int i = 0; i < nc; i++) {
        const float e = expf(lv[i] - MX);
        lv[i] = e;
        sum += e;
    }
    #pragma unroll
    for (int o = 16; o > 0; o >>= 1)
        sum += __shfl_xor_sync(0xFFFFFFFFu, sum, o);
    if ((t & 31) == 0) shsum[t >> 5] = sum;
    __syncthreads();
    float SUM = 0.f;
    #pragma unroll
    for (int w = 0; w < 8; w++) SUM += shsum[w];

    const float inv = 1.0f / SUM;
    for (int i = 0; i < nc; i++) r[t + (i << 8)] = f2tf_f(lv[i] * inv);
}

// ---------------------------------------------------------------------------
// kernel_launch
// ---------------------------------------------------------------------------
extern "C" void kernel_launch(void* const* d_in, const int* in_sizes, int n_in,
                              void* d_out, int out_size)
{
    const float* query    = (const float*)d_in[0];
    const float* memory   = (const float*)d_in[1];
    const float* prevmask = (const float*)d_in[2];
    const float* sa_in_w  = (const float*)d_in[5];
    const float* sa_in_b  = (const float*)d_in[6];
    const float* sa_out_w = (const float*)d_in[7];
    const float* sa_out_b = (const float*)d_in[8];
    const float* ln1_g = (const float*)d_in[9];
    const float* ln1_b = (const float*)d_in[10];
    const float* ln2_g = (const float*)d_in[11];
    const float* ln2_b = (const float*)d_in[12];
    const float* ln3_g = (const float*)d_in[13];
    const float* ln3_b = (const float*)d_in[14];
    const float* wq = (const float*)d_in[15];
    const float* bq = (const float*)d_in[16];
    const float* wk = (const float*)d_in[17];
    // bk (d_in[18]) is mathematically eliminated: its score contribution is
    // constant per softmax row and cancels exactly.
    const float* wv = (const float*)d_in[19];
    const float* bv = (const float*)d_in[20];
    const float* wo = (const float*)d_in[21];
    const float* bo = (const float*)d_in[22];
    const float* w1 = (const float*)d_in[23];
    const float* b1 = (const float*)d_in[24];
    const float* w2 = (const float*)d_in[25];
    const float* b2 = (const float*)d_in[26];
    const float* mask_w = (const float*)d_in[27];
    const float* mask_b = (const float*)d_in[28];

    float* scr = nullptr;
    cudaGetSymbolAddress((void**)&scr, g_scratch);

    float* gx    = scr + OFF_X;
    float* gq    = scr + OFF_PACK;
    float* gk    = scr + OFF_PACK + 2097152LL;
    float* gv    = scr + OFF_PACK + 4194304LL;
    float* gsc   = scr + OFF_SCORES;
    float* gorep = scr + OFF_OREP;
    float* gq1   = scr + OFF_Q1;
    float* gQc   = scr + OFF_QC;
    float* gQp   = scr + OFF_QP;
    float* gq2   = scr + OFF_Q2;
    float* gh    = scr + OFF_H;
    float* gqm   = scr + OFF_QM;
    float* gwkr  = scr + OFF_WKR;

    float* out_q = (float*)d_out;
    float* out_m = out_q + (long long)M_TOK * D_MODEL;

    const float inv_sqrt_hd = 0.088388347648318447f;
    const float inv_sqrt_d  = 0.03125f;

    cudaFuncSetAttribute(gemm_tc<0,0,1,128,1,0>, cudaFuncAttributeMaxDynamicSharedMemorySize, GS_BYTES(128));
    cudaFuncSetAttribute(gemm_tc<0,0,0,128,0,0>, cudaFuncAttributeMaxDynamicSharedMemorySize, GS_BYTES(128));
    cudaFuncSetAttribute(gemm_tc<0,1,0,128,1,0>, cudaFuncAttributeMaxDynamicSharedMemorySize, GS_BYTES(128));
    cudaFuncSetAttribute(gemm_tc<0,2,0,128,0,0>, cudaFuncAttributeMaxDynamicSharedMemorySize, GS_BYTES(128));
    cudaFuncSetAttribute(gemm_tc<1,0,2,64,1,0>,  cudaFuncAttributeMaxDynamicSharedMemorySize, GS_BYTES(64));
    cudaFuncSetAttribute(gemm_tc<0,0,0,64,0,0>,  cudaFuncAttributeMaxDynamicSharedMemorySize, GS_BYTES(64));
    cudaFuncSetAttribute(gemm_tc<0,0,0,64,1,0>,  cudaFuncAttributeMaxDynamicSharedMemorySize, GS_BYTES(64));
    cudaFuncSetAttribute(gemm_tc<1,0,0,64,1,0>,  cudaFuncAttributeMaxDynamicSharedMemorySize, GS_BYTES(64));
    cudaFuncSetAttribute(gemm_tc<0,0,0,64,0,1>,  cudaFuncAttributeMaxDynamicSharedMemorySize, GS_BYTES(64));

    // 0. round wk -> gwkr (used as BLAYOUT=1 operand in Q@wk)
    round4_k<<<1024, 256>>>(wk, gwkr, 262144);

    // 1. ln1(query) (rounds)
    ln_k<<<M_TOK, 256>>>(query, ln1_g, ln1_b, gx);

    // 2. QKV projection + head-pack (rounds)
    gemm_tc<0,0,1,128,1,0><<<dim3(24,16,1), 128, GS_BYTES(128)>>>(gx, sa_in_w, sa_in_b, nullptr,
        gq, nullptr, M_TOK, 3*D_MODEL, D_MODEL, D_MODEL, D_MODEL, 0, 0, 0, 1.0f, 0, 0);

    // 3. self-attn scores (batched 64)
    gemm_tc<0,0,0,128,0,0><<<dim3(2,2,64), 128, GS_BYTES(128)>>>(gq, gk, nullptr, nullptr,
        gsc, nullptr, NQ, NQ, HDIM, HDIM, HDIM, 256LL*128, 256LL*128, 256LL*256,
        inv_sqrt_hd, 0, 0);

    // 4. softmax (rounds)
    softmax_k<<<64*256, 256>>>(gsc, nullptr, 256);

    // 5. o = attn @ v + o-pack (rounds) -> gorep [2048,1024]
    gemm_tc<1,0,2,64,1,0><<<dim3(1,4,64), 128, GS_BYTES(64)>>>(gsc, gv, nullptr, nullptr,
        gorep, nullptr, NQ, HDIM, NQ, NQ, HDIM, 256LL*256, 256LL*128, 0, 1.0f, 0, 0);

    // 6. self out-proj + residual (fp32 exact)
    gemm_tc<0,0,0,64,0,0><<<dim3(8,32,1), 128, GS_BYTES(64)>>>(gorep, sa_out_w, sa_out_b, query,
        gq1, nullptr, M_TOK, D_MODEL, D_MODEL, D_MODEL, D_MODEL, 0, 0, 0, 1.0f, 0, 0);

    // 7. ln2 (rounds)
    ln_k<<<M_TOK, 256>>>(gq1, ln2_g, ln2_b, gx);

    // 8. Q proj -> gQc [B,NQ,D] b-major (rounds)
    gemm_tc<0,0,0,64,1,0><<<dim3(8,32,1), 128, GS_BYTES(64)>>>(gx, wq, bq, nullptr,
        gQc, nullptr, M_TOK, D_MODEL, D_MODEL, D_MODEL, D_MODEL, 0, 0, 0, 1.0f, 8, 256);

    // 9. Q' = Q @ wk  (replaces the entire 68.7 GF K-projection; bk cancels in
    //    softmax). BLAYOUT=1: wk as [K=1024, N=1024]. -> gQp [2048,1024] (rounds)
    gemm_tc<1,0,0,64,1,0><<<dim3(8,32,1), 128, GS_BYTES(64)>>>(gQc, gwkr, nullptr, nullptr,
        gQp, nullptr, M_TOK, D_MODEL, D_MODEL, D_MODEL, D_MODEL, 0, 0, 0, 1.0f, 0, 0);

    // 10. cross scores = Q' @ memory_b^T / sqrt(D)
    //     B = memory rows (s*8+b): Bb = memory + b*1024, ldb = 8192
    gemm_tc<0,0,0,128,0,0><<<dim3(32,2,8), 128, GS_BYTES(128)>>>(gQp, memory, nullptr, nullptr,
        gsc, nullptr, NQ, SEQ_S, D_MODEL, D_MODEL, 8192,
        256LL*1024, 1024LL, 256LL*4096, inv_sqrt_d, 0, 0);

    // 11. softmax + log(prev_mask) (rounds)
    softmax_k<<<BATCH*NQ, 256>>>(gsc, prevmask, SEQ_S);

    // 12. AM = attn @ memory_b  (replaces the 68.7 GF V-projection; attn rows
    //     sum to 1 so bv moves to the next GEMM). BLAYOUT=1, ldb=8192 -> gorep
    gemm_tc<1,0,0,64,1,0><<<dim3(8,4,8), 128, GS_BYTES(64)>>>(gsc, memory, nullptr, nullptr,
        gorep, nullptr, NQ, D_MODEL, SEQ_S, SEQ_S, 8192,
        256LL*4096, 1024LL, 256LL*1024, 1.0f, 0, 0);

    // 13. attn_out = AM @ wv^T + bv -> gQp [2048,1024] b-major (rounds)
    gemm_tc<0,0,0,64,1,0><<<dim3(8,32,1), 128, GS_BYTES(64)>>>(gorep, wv, bv, nullptr,
        gQp, nullptr, M_TOK, D_MODEL, D_MODEL, D_MODEL, D_MODEL, 0, 0, 0, 1.0f, 0, 0);

    // 14. cross out-proj + residual -> [NQ,B,D] (fp32 exact)
    gemm_tc<0,0,0,64,0,0><<<dim3(8,32,1), 128, GS_BYTES(64)>>>(gQp, wo, bo, gq1,
        gq2, nullptr, M_TOK, D_MODEL, D_MODEL, D_MODEL, D_MODEL, 0, 0, 0, 1.0f, 256, 8);

    // 15. ln3 (rounds)
    ln_k<<<M_TOK, 256>>>(gq2, ln3_g, ln3_b, gx);

    // 16. FFN1 + GELU (rounds)
    gemm_tc<0,1,0,128,1,0><<<dim3(32,16,1), 128, GS_BYTES(128)>>>(gx, w1, b1, nullptr,
        gh, nullptr, M_TOK, FF_DIM, D_MODEL, D_MODEL, D_MODEL, 0, 0, 0, 1.0f, 0, 0);

    // 17. FFN2 + residual -> out_q exact; dual rounded gather -> gqm
    gemm_tc<0,0,0,64,0,1><<<dim3(8,32,1), 128, GS_BYTES(64)>>>(gh, w2, b2, gq2,
        out_q, gqm, M_TOK, D_MODEL, FF_DIM, FF_DIM, FF_DIM, 0, 0, 0, 1.0f, 0, 0);

    // 18. mask logits + sigmoid -> out_m
    gemm_tc<0,2,0,128,0,0><<<dim3(32,16,1), 128, GS_BYTES(128)>>>(gqm, mask_w, mask_b, nullptr,
        out_m, nullptr, M_TOK, SEQ_S, D_MODEL, D_MODEL, D_MODEL, 0, 0, 0, 1.0f, 0, 0);
}

// round 14
// speedup vs baseline: 2.1446x; 1.4872x over previous
#include <cuda_runtime.h>
#include <math.h>

// ---------------------------------------------------------------------------
// Problem constants
// ---------------------------------------------------------------------------
#define D_MODEL 1024
#define NHEAD   8
#define HDIM    128
#define NQ      256
#define BATCH   8
#define SEQ_S   4096
#define FF_DIM  4096
#define M_TOK   (NQ*BATCH)       // 2048
#define M_MEM   (SEQ_S*BATCH)    // 32768

// ---------------------------------------------------------------------------
// Scratch (offsets in floats)
// ---------------------------------------------------------------------------
#define OFF_X      0LL                       // ln out [2048,1024]
#define OFF_PACK   2097152LL                 // q,k,v packed [3][64][256][128]
#define OFF_SCORES 8388608LL                 // scores (max 8*256*4096)
#define OFF_OREP   16777216LL                // repacked attn-out / AM [2048,1024]
#define OFF_Q1     18874368LL
#define OFF_QP     20971520LL                // Q' (b-major) [2048,1024]
#define OFF_Q2     23068672LL
#define OFF_H      25165824LL                // FFN hidden [2048,4096]
#define OFF_QM     33554432LL                // query gathered [B,NQ,D]
#define OFF_WKR    35651584LL                // rounded wk [1024,1024]
#define OFF_WQT    36700160LL                // wq^T rounded
#define OFF_WQK    37748736LL                // Wqk = wq^T @ wk
#define OFF_WVO    38797312LL                // Wvo = wo @ wv
#define OFF_BQK    39845888LL                // bqk [1024]
#define OFF_BVO    39846912LL                // bvo [1024]
#define SCRATCH_TOTAL 39847936LL

__device__ float g_scratch[SCRATCH_TOTAL];

// ---------------------------------------------------------------------------
// Helpers
// ---------------------------------------------------------------------------
__device__ __forceinline__ float gelu_exact(float x) {
    return 0.5f * x * (1.0f + erff(x * 0.70710678118654752f));
}
__device__ __forceinline__ float f2tf_f(float x) {
    unsigned u;
    asm("cvt.rna.tf32.f32 %0, %1;" : "=r"(u) : "f"(x));
    return __uint_as_float(u);
}

// ---------------------------------------------------------------------------
// tf32 tensor-core batched GEMM, 4-stage cp.async pipeline.
// 128 threads, 4 warps. CTA tile MTILE x 128 x 16.
//   C = act( alpha * A @ op(B) + bias + resid )
//   BLAYOUT 0: B is [N,K] (A@B^T). BLAYOUT 1: B is [K,N].
//   ACT: 0 none, 1 gelu, 2 sigmoid.
//   PK: 0 normal (permP/permQ remap; DUAL -> extra rounded gather to C2)
//       1 QKV head-pack epilogue    2 self-AV o-pack epilogue
//   RNDC: round C store to tf32 (rna).
//   SWAP: blockIdx.x -> m-tile (partner m-tiles adjacent in dispatch order).
//   ADDLM: add logf(C2[base+gn] + 1e-6) to scores (cross-attn mask fusion).
// Dynamic smem: GSTAGES * (MTILE*20 + 2560) floats.
// ---------------------------------------------------------------------------
#define GSTAGES 4
#define GS_BYTES(MT_) (GSTAGES * ((MT_)*20 + 2560) * 4)

template<int BLAYOUT, int ACT, int PK, int MTILE, int RNDC, int DUAL, int SWAP, int ADDLM>
__global__ void __launch_bounds__(128, 2)
gemm_tc(const float* __restrict__ A, const float* __restrict__ B,
        const float* __restrict__ bias, const float* __restrict__ resid,
        float* __restrict__ C, float* __restrict__ C2,
        int M, int N, int K, int lda, int ldb,
        long long bA, long long bB, long long bC,
        float alpha, int permP, int permQ)
{
    constexpr int MT   = MTILE / 32;
    constexpr int ASTR = MTILE * 20;
    extern __shared__ float smemf[];
    float* As = smemf;
    float* Bs = smemf + GSTAGES * ASTR;

    const int z  = blockIdx.z;
    const float* Ab = A + (long long)z * bA;
    const float* Bb = B + (long long)z * bB;
    const int m0 = (SWAP ? blockIdx.x : blockIdx.y) * MTILE;
    const int n0 = (SWAP ? blockIdx.y : blockIdx.x) * 128;

    const int tid  = threadIdx.x;
    const int lane = tid & 31;
    const int warp = tid >> 5;
    const int warpM = warp >> 1;
    const int warpN = warp & 1;
    const int lr = lane >> 2;
    const int lc = lane & 3;

    const int a_r0 = tid >> 2;
    const int a_kq = (tid & 3) * 4;
    const float* Aptr = Ab + (long long)(m0 + a_r0) * lda + a_kq;

    const float* Bptr;
    int b1_k0 = 0, b1_nq = 0;
    if (BLAYOUT == 0) {
        Bptr = Bb + (long long)(n0 + a_r0) * ldb + a_kq;
    } else {
        b1_k0 = tid >> 5;
        b1_nq = (tid & 31) * 4;
        Bptr = Bb + (long long)b1_k0 * ldb + n0 + b1_nq;
    }

    const unsigned sAu = (unsigned)__cvta_generic_to_shared(As);
    const unsigned sBu = (unsigned)__cvta_generic_to_shared(Bs);
    const unsigned dA0 = sAu + (unsigned)(a_r0 * 20 + a_kq) * 4u;
    const unsigned dB0 = (BLAYOUT == 0)
        ? sBu + (unsigned)(a_r0 * 20 + a_kq) * 4u
        : sBu + (unsigned)(b1_k0 * 136 + b1_nq) * 4u;

    const int nkt = K >> 4;

    auto issue = [&](int kt, int slot) {
        const long long ka = (long long)kt * 16;
        const unsigned soA = (unsigned)slot * (unsigned)ASTR * 4u;
        const unsigned soB = (unsigned)slot * 2560u * 4u;
        #pragma unroll
        for (int i = 0; i < MT; i++) {
            const float* g = Aptr + (long long)i * 32 * lda + ka;
            unsigned d = dA0 + soA + (unsigned)(i * 32 * 20) * 4u;
            asm volatile("cp.async.cg.shared.global [%0], [%1], 16;\n" :: "r"(d), "l"(g));
        }
        if (BLAYOUT == 0) {
            #pragma unroll
            for (int i = 0; i < 4; i++) {
                const float* g = Bptr + (long long)i * 32 * ldb + ka;
                unsigned d = dB0 + soB + (unsigned)(i * 32 * 20) * 4u;
                asm volatile("cp.async.cg.shared.global [%0], [%1], 16;\n" :: "r"(d), "l"(g));
            }
        } else {
            #pragma unroll
            for (int i = 0; i < 4; i++) {
                const float* g = Bptr + (ka + (long long)i * 4) * ldb;
                unsigned d = dB0 + soB + (unsigned)(i * 4 * 136) * 4u;
                asm volatile("cp.async.cg.shared.global [%0], [%1], 16;\n" :: "r"(d), "l"(g));
            }
        }
        asm volatile("cp.async.commit_group;\n");
    };

    float acc[MT][8][4];
    #pragma unroll
    for (int a = 0; a < MT; a++)
        #pragma unroll
        for (int b = 0; b < 8; b++)
            #pragma unroll
            for (int c = 0; c < 4; c++) acc[a][b][c] = 0.f;

    #pragma unroll
    for (int s = 0; s < GSTAGES - 1; s++) {
        if (s < nkt) issue(s, s);
        else asm volatile("cp.async.commit_group;\n");
    }

    for (int kt = 0; kt < nkt; kt++) {
        asm volatile("cp.async.wait_group %0;\n" :: "n"(GSTAGES - 2));
        __syncthreads();

        const int nx = kt + GSTAGES - 1;
        if (nx < nkt) issue(nx, nx & (GSTAGES - 1));
        else asm volatile("cp.async.commit_group;\n");

        const float* Asb = As + (kt & (GSTAGES - 1)) * ASTR;
        const float* Bsb = Bs + (kt & (GSTAGES - 1)) * 2560;

        #pragma unroll
        for (int k8 = 0; k8 < 2; k8++) {
            const int c = k8 * 8 + lc;
            unsigned bf[8][2];
            #pragma unroll
            for (int nt = 0; nt < 8; nt++) {
                if (BLAYOUT == 0) {
                    const int nn = warpN*64 + nt*8 + lr;
                    bf[nt][0] = __float_as_uint(Bsb[nn*20 + c]);
                    bf[nt][1] = __float_as_uint(Bsb[nn*20 + c + 4]);
                } else {
                    const int kk = k8*8 + lc;
                    const int nn = warpN*64 + nt*8 + lr;
                    bf[nt][0] = __float_as_uint(Bsb[kk*136 + nn]);
                    bf[nt][1] = __float_as_uint(Bsb[(kk+4)*136 + nn]);
                }
            }
            #pragma unroll
            for (int mt = 0; mt < MT; mt++) {
                const int r = warpM*(MTILE/2) + mt*16 + lr;
                unsigned a0 = __float_as_uint(Asb[r*20 + c]);
                unsigned a1 = __float_as_uint(Asb[(r+8)*20 + c]);
                unsigned a2 = __float_as_uint(Asb[r*20 + c + 4]);
                unsigned a3 = __float_as_uint(Asb[(r+8)*20 + c + 4]);
                #pragma unroll
                for (int nt = 0; nt < 8; nt++) {
                    asm volatile(
                        "mma.sync.aligned.m16n8k8.row.col.f32.tf32.tf32.f32 "
                        "{%0,%1,%2,%3}, {%4,%5,%6,%7}, {%8,%9}, {%0,%1,%2,%3};"
                        : "+f"(acc[mt][nt][0]), "+f"(acc[mt][nt][1]),
                          "+f"(acc[mt][nt][2]), "+f"(acc[mt][nt][3])
                        : "r"(a0), "r"(a1), "r"(a2), "r"(a3),
                          "r"(bf[nt][0]), "r"(bf[nt][1]));
                }
            }
        }
    }

    // ---- epilogue ----
    #pragma unroll
    for (int mt = 0; mt < MT; mt++) {
        #pragma unroll
        for (int h = 0; h < 2; h++) {
            const int gm = m0 + warpM*(MTILE/2) + mt*16 + lr + h*8;
            #pragma unroll
            for (int nt = 0; nt < 8; nt++) {
                const int gn = n0 + warpN*64 + nt*8 + 2*lc;
                float v0 = acc[mt][nt][2*h+0] * alpha;
                float v1 = acc[mt][nt][2*h+1] * alpha;
                if (PK != 2) {
                    if (bias) { v0 += bias[gn]; v1 += bias[gn+1]; }
                }
                if (PK == 1) {
                    const int b = gm & 7, l = gm >> 3;
                    const int sec = gn >> 10, hh = (gn >> 7) & 7, d = gn & 127;
                    const long long idx = (long long)sec * 2097152LL
                        + ((long long)(b*8 + hh) * 256 + l) * 128 + d;
                    if (RNDC) { v0 = f2tf_f(v0); v1 = f2tf_f(v1); }
                    float2 o; o.x = v0; o.y = v1;
                    *(float2*)(&C[idx]) = o;
                } else if (PK == 2) {
                    const int b = z >> 3, hh = z & 7;
                    const long long idx = ((long long)(gm*8 + b)) * 1024 + hh*128 + gn;
                    if (RNDC) { v0 = f2tf_f(v0); v1 = f2tf_f(v1); }
                    float2 o; o.x = v0; o.y = v1;
                    *(float2*)(&C[idx]) = o;
                } else {
                    const int rm = (permP > 0) ? ((gm % permP) * permQ + gm / permP) : gm;
                    const long long base = (long long)z * bC + (long long)rm * N;
                    if (ADDLM) {
                        v0 += logf(C2[base + gn] + 1e-6f);
                        v1 += logf(C2[base + gn + 1] + 1e-6f);
                    }
                    if (resid) { v0 += resid[base + gn]; v1 += resid[base + gn + 1]; }
                    if (ACT == 1) { v0 = gelu_exact(v0); v1 = gelu_exact(v1); }
                    else if (ACT == 2) {
                        v0 = 1.0f / (1.0f + expf(-v0));
                        v1 = 1.0f / (1.0f + expf(-v1));
                    }
                    float2 o;
                    if (RNDC) { o.x = f2tf_f(v0); o.y = f2tf_f(v1); }
                    else      { o.x = v0; o.y = v1; }
                    *(float2*)(&C[base + gn]) = o;
                    if (DUAL) {
                        const int r2 = (gm & 7) * 256 + (gm >> 3);
                        float2 o2; o2.x = f2tf_f(v0); o2.y = f2tf_f(v1);
                        *(float2*)(&C2[(long long)r2 * N + gn]) = o2;
                    }
                }
            }
        }
    }
}

// ---------------------------------------------------------------------------
// tf32 rounding pass (float4)
// ---------------------------------------------------------------------------
__global__ void round4_k(const float* __restrict__ in, float* __restrict__ out, int n4)
{
    const int i = blockIdx.x * 256 + threadIdx.x;
    if (i < n4) {
        float4 v = ((const float4*)in)[i];
        v.x = f2tf_f(v.x); v.y = f2tf_f(v.y);
        v.z = f2tf_f(v.z); v.w = f2tf_f(v.w);
        ((float4*)out)[i] = v;
    }
}

// ---------------------------------------------------------------------------
// 1024x1024 transpose (rounds output)
// ---------------------------------------------------------------------------
__global__ void transpose_k(const float* __restrict__ in, float* __restrict__ out)
{
    __shared__ float t[32][33];
    const int bx = blockIdx.x * 32, by = blockIdx.y * 32;
    #pragma unroll
    for (int i = 0; i < 32; i += 8)
        t[threadIdx.y + i][threadIdx.x] =
            in[(long long)(by + threadIdx.y + i) * 1024 + bx + threadIdx.x];
    __syncthreads();
    #pragma unroll
    for (int i = 0; i < 32; i += 8)
        out[(long long)(bx + threadIdx.y + i) * 1024 + by + threadIdx.x] =
            f2tf_f(t[threadIdx.x][threadIdx.y + i]);
}

// ---------------------------------------------------------------------------
// bqk[j] = sum_i bq[i] * wkr[i,j]    (grid 4 x 256)
// ---------------------------------------------------------------------------
__global__ void bqk_k(const float* __restrict__ bq, const float* __restrict__ wkr,
                      float* __restrict__ outb)
{
    const int j = blockIdx.x * 256 + threadIdx.x;
    float s = 0.f;
    for (int i = 0; i < 1024; i++) s += bq[i] * wkr[(long long)i * 1024 + j];
    outb[j] = s;
}

// ---------------------------------------------------------------------------
// bvo[n] = bo[n] + sum_i wo[n,i] * bv[i]   (one warp per n; grid 128 x 256)
// ---------------------------------------------------------------------------
__global__ void bvo_k(const float* __restrict__ wo, const float* __restrict__ bv,
                      const float* __restrict__ bo, float* __restrict__ outb)
{
    const int w = threadIdx.x >> 5, l = threadIdx.x & 31;
    const int n = blockIdx.x * 8 + w;
    float s = 0.f;
    for (int i = l; i < 1024; i += 32) s += wo[(long long)n * 1024 + i] * bv[i];
    #pragma unroll
    for (int o = 16; o > 0; o >>= 1) s += __shfl_xor_sync(0xFFFFFFFFu, s, o);
    if (l == 0) outb[n] = s + bo[n];
}

// ---------------------------------------------------------------------------
// LayerNorm over D=1024 (output tf32-rounded)
// ---------------------------------------------------------------------------
__global__ void ln_k(const float* __restrict__ x, const float* __restrict__ g,
                     const float* __restrict__ b, float* __restrict__ y)
{
    const long long row = blockIdx.x;
    const float* xr = x + row * D_MODEL;
    float* yr = y + row * D_MODEL;
    const int t = threadIdx.x;

    float v[4], s = 0.f, s2 = 0.f;
    #pragma unroll
    for (int i = 0; i < 4; i++) {
        v[i] = xr[t + i * 256];
        s  += v[i];
        s2 += v[i] * v[i];
    }
    #pragma unroll
    for (int o = 16; o > 0; o >>= 1) {
        s  += __shfl_xor_sync(0xFFFFFFFFu, s,  o);
        s2 += __shfl_xor_sync(0xFFFFFFFFu, s2, o);
    }
    __shared__ float shs[8], shs2[8];
    if ((t & 31) == 0) { shs[t >> 5] = s; shs2[t >> 5] = s2; }
    __syncthreads();
    float S = 0.f, S2 = 0.f;
    #pragma unroll
    for (int w = 0; w < 8; w++) { S += shs[w]; S2 += shs2[w]; }

    const float mean = S * (1.0f / D_MODEL);
    const float var  = S2 * (1.0f / D_MODEL) - mean * mean;
    const float inv  = rsqrtf(var + 1e-5f);
    #pragma unroll
    for (int i = 0; i < 4; i++) {
        const int c = t + i * 256;
        yr[c] = f2tf_f((v[i] - mean) * inv * g[c] + b[c]);
    }
}

// ---------------------------------------------------------------------------
// Row softmax in-place fp32 (optionally + log(prev_mask + 1e-6)); tf32 out
// ---------------------------------------------------------------------------
__global__ void softmax_k(float* __restrict__ s, const float* __restrict__ pm, int cols)
{
    const long long row = blockIdx.x;
    float* r = s + row * cols;
    const float* pmr = pm ? pm + row * cols : nullptr;
    const int t = threadIdx.x;
    const int nc = cols >> 8;

    float lv[16];
    float mx = -1e30f;
    for (int i = 0; i < nc; i++) {
        float v = r[t + (i << 8)];
        if (pmr) v += logf(pmr[t + (i << 8)] + 1e-6f);
        lv[i] = v;
        mx = fmaxf(mx, v);
    }
    #pragma unroll
    for (int o = 16; o > 0; o >>= 1)
        mx = fmaxf(mx, __shfl_xor_sync(0xFFFFFFFFu, mx, o));
    __shared__ float shm[8], shsum[8];
    if ((t & 31) == 0) shm[t >> 5] = mx;
    __syncthreads();
    float MX = shm[0];
    #pragma unroll
    for (int w = 1; w < 8; w++) MX = fmaxf(MX, shm[w]);

    float sum = 0.f;
    for (int i = 0; i < nc; i++) {
        const float e = expf(lv[i] - MX);
        lv[i] = e;
        sum += e;
    }
    #pragma unroll
    for (int o = 16; o > 0; o >>= 1)
        sum += __shfl_xor_sync(0xFFFFFFFFu, sum, o);
    if ((t & 31) == 0) shsum[t >> 5] = sum;
    __syncthreads();
    float SUM = 0.f;
    #pragma unroll
    for (int w = 0; w < 8; w++) SUM += shsum[w];

    const float inv = 1.0f / SUM;
    for (int i = 0; i < nc; i++) r[t + (i << 8)] = f2tf_f(lv[i] * inv);
}

// ---------------------------------------------------------------------------
// kernel_launch
// ---------------------------------------------------------------------------
extern "C" void kernel_launch(void* const* d_in, const int* in_sizes, int n_in,
                              void* d_out, int out_size)
{
    const float* query    = (const float*)d_in[0];
    const float* memory   = (const float*)d_in[1];
    const float* prevmask = (const float*)d_in[2];
    const float* sa_in_w  = (const float*)d_in[5];
    const float* sa_in_b  = (const float*)d_in[6];
    const float* sa_out_w = (const float*)d_in[7];
    const float* sa_out_b = (const float*)d_in[8];
    const float* ln1_g = (const float*)d_in[9];
    const float* ln1_b = (const float*)d_in[10];
    const float* ln2_g = (const float*)d_in[11];
    const float* ln2_b = (const float*)d_in[12];
    const float* ln3_g = (const float*)d_in[13];
    const float* ln3_b = (const float*)d_in[14];
    const float* wq = (const float*)d_in[15];
    const float* bq = (const float*)d_in[16];
    const float* wk = (const float*)d_in[17];
    // bk eliminated: its score contribution is constant per softmax row.
    const float* wv = (const float*)d_in[19];
    const float* bv = (const float*)d_in[20];
    const float* wo = (const float*)d_in[21];
    const float* bo = (const float*)d_in[22];
    const float* w1 = (const float*)d_in[23];
    const float* b1 = (const float*)d_in[24];
    const float* w2 = (const float*)d_in[25];
    const float* b2 = (const float*)d_in[26];
    const float* mask_w = (const float*)d_in[27];
    const float* mask_b = (const float*)d_in[28];

    float* scr = nullptr;
    cudaGetSymbolAddress((void**)&scr, g_scratch);

    float* gx    = scr + OFF_X;
    float* gq    = scr + OFF_PACK;
    float* gk    = scr + OFF_PACK + 2097152LL;
    float* gv    = scr + OFF_PACK + 4194304LL;
    float* gsc   = scr + OFF_SCORES;
    float* gorep = scr + OFF_OREP;
    float* gq1   = scr + OFF_Q1;
    float* gQp   = scr + OFF_QP;
    float* gq2   = scr + OFF_Q2;
    float* gh    = scr + OFF_H;
    float* gqm   = scr + OFF_QM;
    float* gwkr  = scr + OFF_WKR;
    float* gwqT  = scr + OFF_WQT;
    float* gWqk  = scr + OFF_WQK;
    float* gWvo  = scr + OFF_WVO;
    float* gbqk  = scr + OFF_BQK;
    float* gbvo  = scr + OFF_BVO;

    float* out_q = (float*)d_out;
    float* out_m = out_q + (long long)M_TOK * D_MODEL;

    const float inv_sqrt_hd = 0.088388347648318447f;
    const float inv_sqrt_d  = 0.03125f;

    cudaFuncSetAttribute(gemm_tc<0,0,1,128,1,0,0,0>, cudaFuncAttributeMaxDynamicSharedMemorySize, GS_BYTES(128));
    cudaFuncSetAttribute(gemm_tc<0,0,0,128,0,0,0,0>, cudaFuncAttributeMaxDynamicSharedMemorySize, GS_BYTES(128));
    cudaFuncSetAttribute(gemm_tc<1,0,2,64,1,0,0,0>,  cudaFuncAttributeMaxDynamicSharedMemorySize, GS_BYTES(64));
    cudaFuncSetAttribute(gemm_tc<0,0,0,64,0,0,0,0>,  cudaFuncAttributeMaxDynamicSharedMemorySize, GS_BYTES(64));
    cudaFuncSetAttribute(gemm_tc<1,0,0,64,1,0,0,0>,  cudaFuncAttributeMaxDynamicSharedMemorySize, GS_BYTES(64));
    cudaFuncSetAttribute(gemm_tc<0,0,0,128,0,0,1,1>, cudaFuncAttributeMaxDynamicSharedMemorySize, GS_BYTES(128));
    cudaFuncSetAttribute(gemm_tc<1,0,0,128,1,0,1,0>, cudaFuncAttributeMaxDynamicSharedMemorySize, GS_BYTES(128));
    cudaFuncSetAttribute(gemm_tc<0,1,0,128,1,0,0,0>, cudaFuncAttributeMaxDynamicSharedMemorySize, GS_BYTES(128));
    cudaFuncSetAttribute(gemm_tc<0,0,0,64,0,1,0,0>,  cudaFuncAttributeMaxDynamicSharedMemorySize, GS_BYTES(64));
    cudaFuncSetAttribute(gemm_tc<0,2,0,128,0,0,0,0>, cudaFuncAttributeMaxDynamicSharedMemorySize, GS_BYTES(128));

    // --- weight precomputes ---
    // wk rounded
    round4_k<<<1024, 256>>>(wk, gwkr, 262144);
    // wq^T (rounded)
    transpose_k<<<dim3(32,32), dim3(32,8)>>>(wq, gwqT);
    // Wqk = wq^T @ wk  [1024,1024]
    gemm_tc<1,0,0,64,1,0,0,0><<<dim3(8,16,1), 128, GS_BYTES(64)>>>(gwqT, gwkr, nullptr, nullptr,
        gWqk, nullptr, 1024, 1024, 1024, 1024, 1024, 0, 0, 0, 1.0f, 0, 0);
    // bqk = bq @ wk
    bqk_k<<<4, 256>>>(bq, gwkr, gbqk);
    // Wvo = wo @ wv  [n,m]
    gemm_tc<1,0,0,64,1,0,0,0><<<dim3(8,16,1), 128, GS_BYTES(64)>>>(wo, wv, nullptr, nullptr,
        gWvo, nullptr, 1024, 1024, 1024, 1024, 1024, 0, 0, 0, 1.0f, 0, 0);
    // bvo = wo @ bv + bo
    bvo_k<<<128, 256>>>(wo, bv, bo, gbvo);

    // 1. ln1(query) (rounds)
    ln_k<<<M_TOK, 256>>>(query, ln1_g, ln1_b, gx);

    // 2. QKV projection + head-pack (rounds)
    gemm_tc<0,0,1,128,1,0,0,0><<<dim3(24,16,1), 128, GS_BYTES(128)>>>(gx, sa_in_w, sa_in_b, nullptr,
        gq, nullptr, M_TOK, 3*D_MODEL, D_MODEL, D_MODEL, D_MODEL, 0, 0, 0, 1.0f, 0, 0);

    // 3. self-attn scores (batched 64)
    gemm_tc<0,0,0,128,0,0,0,0><<<dim3(2,2,64), 128, GS_BYTES(128)>>>(gq, gk, nullptr, nullptr,
        gsc, nullptr, NQ, NQ, HDIM, HDIM, HDIM, 256LL*128, 256LL*128, 256LL*256,
        inv_sqrt_hd, 0, 0);

    // 4. softmax (rounds)
    softmax_k<<<64*256, 256>>>(gsc, nullptr, 256);

    // 5. o = attn @ v + o-pack (rounds) -> gorep [2048,1024]
    gemm_tc<1,0,2,64,1,0,0,0><<<dim3(1,4,64), 128, GS_BYTES(64)>>>(gsc, gv, nullptr, nullptr,
        gorep, nullptr, NQ, HDIM, NQ, NQ, HDIM, 256LL*256, 256LL*128, 0, 1.0f, 0, 0);

    // 6. self out-proj + residual (fp32 exact)
    gemm_tc<0,0,0,64,0,0,0,0><<<dim3(8,32,1), 128, GS_BYTES(64)>>>(gorep, sa_out_w, sa_out_b, query,
        gq1, nullptr, M_TOK, D_MODEL, D_MODEL, D_MODEL, D_MODEL, 0, 0, 0, 1.0f, 0, 0);

    // 7. ln2 (rounds)
    ln_k<<<M_TOK, 256>>>(gq1, ln2_g, ln2_b, gx);

    // 8. Q' = ln2 @ Wqk + bqk  -> gQp b-major (rounds)  [replaces Qproj + Q@wk]
    gemm_tc<1,0,0,64,1,0,0,0><<<dim3(8,32,1), 128, GS_BYTES(64)>>>(gx, gWqk, gbqk, nullptr,
        gQp, nullptr, M_TOK, D_MODEL, D_MODEL, D_MODEL, D_MODEL, 0, 0, 0, 1.0f, 8, 256);

    // 10. cross scores = Q' @ memory_b^T / sqrt(D)  + log(prev_mask) fused
    gemm_tc<0,0,0,128,0,0,1,1><<<dim3(2,32,8), 128, GS_BYTES(128)>>>(gQp, memory, nullptr, nullptr,
        gsc, (float*)prevmask, NQ, SEQ_S, D_MODEL, D_MODEL, 8192,
        256LL*1024, 1024LL, 256LL*4096, inv_sqrt_d, 0, 0);

    // 11. softmax (mask already added) (rounds)
    softmax_k<<<BATCH*NQ, 256>>>(gsc, nullptr, SEQ_S);

    // 12. AM = attn @ memory_b (rounds), MTILE=128, partner m-tiles adjacent
    gemm_tc<1,0,0,128,1,0,1,0><<<dim3(2,8,8), 128, GS_BYTES(128)>>>(gsc, memory, nullptr, nullptr,
        gorep, nullptr, NQ, D_MODEL, SEQ_S, SEQ_S, 8192,
        256LL*4096, 1024LL, 256LL*1024, 1.0f, 0, 0);

    // 13. out = AM @ Wvo^T + bvo + resid -> [NQ,B,D] (fp32 exact)
    //     [replaces AM@wv^T and out-proj]
    gemm_tc<0,0,0,64,0,0,0,0><<<dim3(8,32,1), 128, GS_BYTES(64)>>>(gorep, gWvo, gbvo, gq1,
        gq2, nullptr, M_TOK, D_MODEL, D_MODEL, D_MODEL, D_MODEL, 0, 0, 0, 1.0f, 256, 8);

    // 14. ln3 (rounds)
    ln_k<<<M_TOK, 256>>>(gq2, ln3_g, ln3_b, gx);

    // 15. FFN1 + GELU (rounds)
    gemm_tc<0,1,0,128,1,0,0,0><<<dim3(32,16,1), 128, GS_BYTES(128)>>>(gx, w1, b1, nullptr,
        gh, nullptr, M_TOK, FF_DIM, D_MODEL, D_MODEL, D_MODEL, 0, 0, 0, 1.0f, 0, 0);

    // 16. FFN2 + residual -> out_q exact; dual rounded gather -> gqm
    gemm_tc<0,0,0,64,0,1,0,0><<<dim3(8,32,1), 128, GS_BYTES(64)>>>(gh, w2, b2, gq2,
        out_q, gqm, M_TOK, D_MODEL, FF_DIM, FF_DIM, FF_DIM, 0, 0, 0, 1.0f, 0, 0);

    // 17. mask logits + sigmoid -> out_m
    gemm_tc<0,2,0,128,0,0,0,0><<<dim3(32,16,1), 128, GS_BYTES(128)>>>(gqm, mask_w, mask_b, nullptr,
        out_m, nullptr, M_TOK, SEQ_S, D_MODEL, D_MODEL, D_MODEL, 0, 0, 0, 1.0f, 0, 0);
}

// round 15
// speedup vs baseline: 2.1896x; 1.0210x over previous
#include <cuda_runtime.h>
#include <math.h>

// ---------------------------------------------------------------------------
// Problem constants
// ---------------------------------------------------------------------------
#define D_MODEL 1024
#define NHEAD   8
#define HDIM    128
#define NQ      256
#define BATCH   8
#define SEQ_S   4096
#define FF_DIM  4096
#define M_TOK   (NQ*BATCH)       // 2048
#define M_MEM   (SEQ_S*BATCH)    // 32768

// ---------------------------------------------------------------------------
// Scratch (offsets in floats)
// ---------------------------------------------------------------------------
#define OFF_X      0LL                       // ln out [2048,1024]
#define OFF_PACK   2097152LL                 // q,k,v packed [3][64][256][128]
#define OFF_SCORES 8388608LL                 // scores (max 8*256*4096)
#define OFF_OREP   16777216LL                // repacked attn-out / AM [2048,1024]
#define OFF_Q1     18874368LL
#define OFF_QP     20971520LL                // Q' (b-major) [2048,1024]
#define OFF_Q2     23068672LL
#define OFF_H      25165824LL                // FFN hidden [2048,4096]
#define OFF_QM     33554432LL                // query gathered [B,NQ,D]
#define OFF_WKR    35651584LL                // rounded wk [1024,1024]
#define OFF_WQT    36700160LL                // wq^T rounded
#define OFF_WQK    37748736LL                // Wqk = wq^T @ wk
#define OFF_WVO    38797312LL                // Wvo = wo @ wv
#define OFF_BQK    39845888LL                // bqk [1024]
#define OFF_BVO    39846912LL                // bvo [1024]
#define SCRATCH_TOTAL 39847936LL

__device__ float g_scratch[SCRATCH_TOTAL];

// ---------------------------------------------------------------------------
// Helpers
// ---------------------------------------------------------------------------
__device__ __forceinline__ float gelu_exact(float x) {
    return 0.5f * x * (1.0f + erff(x * 0.70710678118654752f));
}
__device__ __forceinline__ float f2tf_f(float x) {
    unsigned u;
    asm("cvt.rna.tf32.f32 %0, %1;" : "=r"(u) : "f"(x));
    return __uint_as_float(u);
}

// ---------------------------------------------------------------------------
// tf32 tensor-core batched GEMM, 4-stage cp.async pipeline.
// 128 threads, 4 warps. CTA tile MTILE x 128 x 16.
//   C = act( alpha * A @ op(B) + bias + resid )
//   BLAYOUT 0: B is [N,K] (A@B^T). BLAYOUT 1: B is [K,N].
//   ACT: 0 none, 1 gelu, 2 sigmoid.
//   PK: 0 normal (permP/permQ remap; DUAL -> extra rounded gather to C2)
//       1 QKV head-pack epilogue    2 self-AV o-pack epilogue
//   RNDC: round C store to tf32 (rna).
//   SWAP: blockIdx.x -> m-tile (partner m-tiles adjacent in dispatch order).
//   ADDLM: add logf(C2[base+gn] + 1e-6) to scores (cross-attn mask fusion).
// Dynamic smem: GSTAGES * (MTILE*20 + 2560) floats.
// ---------------------------------------------------------------------------
#define GSTAGES 4
#define GS_BYTES(MT_) (GSTAGES * ((MT_)*20 + 2560) * 4)

template<int BLAYOUT, int ACT, int PK, int MTILE, int RNDC, int DUAL, int SWAP, int ADDLM>
__global__ void __launch_bounds__(128, 2)
gemm_tc(const float* __restrict__ A, const float* __restrict__ B,
        const float* __restrict__ bias, const float* __restrict__ resid,
        float* __restrict__ C, float* __restrict__ C2,
        int M, int N, int K, int lda, int ldb,
        long long bA, long long bB, long long bC,
        float alpha, int permP, int permQ)
{
    constexpr int MT   = MTILE / 32;
    constexpr int ASTR = MTILE * 20;
    extern __shared__ float smemf[];
    float* As = smemf;
    float* Bs = smemf + GSTAGES * ASTR;

    const int z  = blockIdx.z;
    const float* Ab = A + (long long)z * bA;
    const float* Bb = B + (long long)z * bB;
    const int m0 = (SWAP ? blockIdx.x : blockIdx.y) * MTILE;
    const int n0 = (SWAP ? blockIdx.y : blockIdx.x) * 128;

    const int tid  = threadIdx.x;
    const int lane = tid & 31;
    const int warp = tid >> 5;
    const int warpM = warp >> 1;
    const int warpN = warp & 1;
    const int lr = lane >> 2;
    const int lc = lane & 3;

    const int a_r0 = tid >> 2;
    const int a_kq = (tid & 3) * 4;
    const float* Aptr = Ab + (long long)(m0 + a_r0) * lda + a_kq;

    const float* Bptr;
    int b1_k0 = 0, b1_nq = 0;
    if (BLAYOUT == 0) {
        Bptr = Bb + (long long)(n0 + a_r0) * ldb + a_kq;
    } else {
        b1_k0 = tid >> 5;
        b1_nq = (tid & 31) * 4;
        Bptr = Bb + (long long)b1_k0 * ldb + n0 + b1_nq;
    }

    const unsigned sAu = (unsigned)__cvta_generic_to_shared(As);
    const unsigned sBu = (unsigned)__cvta_generic_to_shared(Bs);
    const unsigned dA0 = sAu + (unsigned)(a_r0 * 20 + a_kq) * 4u;
    const unsigned dB0 = (BLAYOUT == 0)
        ? sBu + (unsigned)(a_r0 * 20 + a_kq) * 4u
        : sBu + (unsigned)(b1_k0 * 136 + b1_nq) * 4u;

    const int nkt = K >> 4;

    auto issue = [&](int kt, int slot) {
        const long long ka = (long long)kt * 16;
        const unsigned soA = (unsigned)slot * (unsigned)ASTR * 4u;
        const unsigned soB = (unsigned)slot * 2560u * 4u;
        #pragma unroll
        for (int i = 0; i < MT; i++) {
            const float* g = Aptr + (long long)i * 32 * lda + ka;
            unsigned d = dA0 + soA + (unsigned)(i * 32 * 20) * 4u;
            asm volatile("cp.async.cg.shared.global [%0], [%1], 16;\n" :: "r"(d), "l"(g));
        }
        if (BLAYOUT == 0) {
            #pragma unroll
            for (int i = 0; i < 4; i++) {
                const float* g = Bptr + (long long)i * 32 * ldb + ka;
                unsigned d = dB0 + soB + (unsigned)(i * 32 * 20) * 4u;
                asm volatile("cp.async.cg.shared.global [%0], [%1], 16;\n" :: "r"(d), "l"(g));
            }
        } else {
            #pragma unroll
            for (int i = 0; i < 4; i++) {
                const float* g = Bptr + (ka + (long long)i * 4) * ldb;
                unsigned d = dB0 + soB + (unsigned)(i * 4 * 136) * 4u;
                asm volatile("cp.async.cg.shared.global [%0], [%1], 16;\n" :: "r"(d), "l"(g));
            }
        }
        asm volatile("cp.async.commit_group;\n");
    };

    float acc[MT][8][4];
    #pragma unroll
    for (int a = 0; a < MT; a++)
        #pragma unroll
        for (int b = 0; b < 8; b++)
            #pragma unroll
            for (int c = 0; c < 4; c++) acc[a][b][c] = 0.f;

    #pragma unroll
    for (int s = 0; s < GSTAGES - 1; s++) {
        if (s < nkt) issue(s, s);
        else asm volatile("cp.async.commit_group;\n");
    }

    for (int kt = 0; kt < nkt; kt++) {
        asm volatile("cp.async.wait_group %0;\n" :: "n"(GSTAGES - 2));
        __syncthreads();

        const int nx = kt + GSTAGES - 1;
        if (nx < nkt) issue(nx, nx & (GSTAGES - 1));
        else asm volatile("cp.async.commit_group;\n");

        const float* Asb = As + (kt & (GSTAGES - 1)) * ASTR;
        const float* Bsb = Bs + (kt & (GSTAGES - 1)) * 2560;

        #pragma unroll
        for (int k8 = 0; k8 < 2; k8++) {
            const int c = k8 * 8 + lc;
            unsigned bf[8][2];
            #pragma unroll
            for (int nt = 0; nt < 8; nt++) {
                if (BLAYOUT == 0) {
                    const int nn = warpN*64 + nt*8 + lr;
                    bf[nt][0] = __float_as_uint(Bsb[nn*20 + c]);
                    bf[nt][1] = __float_as_uint(Bsb[nn*20 + c + 4]);
                } else {
                    const int kk = k8*8 + lc;
                    const int nn = warpN*64 + nt*8 + lr;
                    bf[nt][0] = __float_as_uint(Bsb[kk*136 + nn]);
                    bf[nt][1] = __float_as_uint(Bsb[(kk+4)*136 + nn]);
                }
            }
            #pragma unroll
            for (int mt = 0; mt < MT; mt++) {
                const int r = warpM*(MTILE/2) + mt*16 + lr;
                unsigned a0 = __float_as_uint(Asb[r*20 + c]);
                unsigned a1 = __float_as_uint(Asb[(r+8)*20 + c]);
                unsigned a2 = __float_as_uint(Asb[r*20 + c + 4]);
                unsigned a3 = __float_as_uint(Asb[(r+8)*20 + c + 4]);
                #pragma unroll
                for (int nt = 0; nt < 8; nt++) {
                    asm volatile(
                        "mma.sync.aligned.m16n8k8.row.col.f32.tf32.tf32.f32 "
                        "{%0,%1,%2,%3}, {%4,%5,%6,%7}, {%8,%9}, {%0,%1,%2,%3};"
                        : "+f"(acc[mt][nt][0]), "+f"(acc[mt][nt][1]),
                          "+f"(acc[mt][nt][2]), "+f"(acc[mt][nt][3])
                        : "r"(a0), "r"(a1), "r"(a2), "r"(a3),
                          "r"(bf[nt][0]), "r"(bf[nt][1]));
                }
            }
        }
    }

    // ---- epilogue ----
    #pragma unroll
    for (int mt = 0; mt < MT; mt++) {
        #pragma unroll
        for (int h = 0; h < 2; h++) {
            const int gm = m0 + warpM*(MTILE/2) + mt*16 + lr + h*8;
            #pragma unroll
            for (int nt = 0; nt < 8; nt++) {
                const int gn = n0 + warpN*64 + nt*8 + 2*lc;
                float v0 = acc[mt][nt][2*h+0] * alpha;
                float v1 = acc[mt][nt][2*h+1] * alpha;
                if (PK != 2) {
                    if (bias) { v0 += bias[gn]; v1 += bias[gn+1]; }
                }
                if (PK == 1) {
                    const int b = gm & 7, l = gm >> 3;
                    const int sec = gn >> 10, hh = (gn >> 7) & 7, d = gn & 127;
                    const long long idx = (long long)sec * 2097152LL
                        + ((long long)(b*8 + hh) * 256 + l) * 128 + d;
                    if (RNDC) { v0 = f2tf_f(v0); v1 = f2tf_f(v1); }
                    float2 o; o.x = v0; o.y = v1;
                    *(float2*)(&C[idx]) = o;
                } else if (PK == 2) {
                    const int b = z >> 3, hh = z & 7;
                    const long long idx = ((long long)(gm*8 + b)) * 1024 + hh*128 + gn;
                    if (RNDC) { v0 = f2tf_f(v0); v1 = f2tf_f(v1); }
                    float2 o; o.x = v0; o.y = v1;
                    *(float2*)(&C[idx]) = o;
                } else {
                    const int rm = (permP > 0) ? ((gm % permP) * permQ + gm / permP) : gm;
                    const long long base = (long long)z * bC + (long long)rm * N;
                    if (ADDLM) {
                        v0 += logf(C2[base + gn] + 1e-6f);
                        v1 += logf(C2[base + gn + 1] + 1e-6f);
                    }
                    if (resid) { v0 += resid[base + gn]; v1 += resid[base + gn + 1]; }
                    if (ACT == 1) { v0 = gelu_exact(v0); v1 = gelu_exact(v1); }
                    else if (ACT == 2) {
                        v0 = 1.0f / (1.0f + expf(-v0));
                        v1 = 1.0f / (1.0f + expf(-v1));
                    }
                    float2 o;
                    if (RNDC) { o.x = f2tf_f(v0); o.y = f2tf_f(v1); }
                    else      { o.x = v0; o.y = v1; }
                    *(float2*)(&C[base + gn]) = o;
                    if (DUAL) {
                        const int r2 = (gm & 7) * 256 + (gm >> 3);
                        float2 o2; o2.x = f2tf_f(v0); o2.y = f2tf_f(v1);
                        *(float2*)(&C2[(long long)r2 * N + gn]) = o2;
                    }
                }
            }
        }
    }
}

// ---------------------------------------------------------------------------
// tf32 rounding pass (float4)
// ---------------------------------------------------------------------------
__global__ void round4_k(const float* __restrict__ in, float* __restrict__ out, int n4)
{
    const int i = blockIdx.x * 256 + threadIdx.x;
    if (i < n4) {
        float4 v = ((const float4*)in)[i];
        v.x = f2tf_f(v.x); v.y = f2tf_f(v.y);
        v.z = f2tf_f(v.z); v.w = f2tf_f(v.w);
        ((float4*)out)[i] = v;
    }
}

// ---------------------------------------------------------------------------
// 1024x1024 transpose (rounds output)
// ---------------------------------------------------------------------------
__global__ void transpose_k(const float* __restrict__ in, float* __restrict__ out)
{
    __shared__ float t[32][33];
    const int bx = blockIdx.x * 32, by = blockIdx.y * 32;
    #pragma unroll
    for (int i = 0; i < 32; i += 8)
        t[threadIdx.y + i][threadIdx.x] =
            in[(long long)(by + threadIdx.y + i) * 1024 + bx + threadIdx.x];
    __syncthreads();
    #pragma unroll
    for (int i = 0; i < 32; i += 8)
        out[(long long)(bx + threadIdx.y + i) * 1024 + by + threadIdx.x] =
            f2tf_f(t[threadIdx.x][threadIdx.y + i]);
}

// ---------------------------------------------------------------------------
// bqk[j] = sum_i bq[i] * wkr[i,j]
// grid 32, block (32,8): x = j within 32-col group (coalesced), y = i-partial.
// ---------------------------------------------------------------------------
__global__ void bqk_k(const float* __restrict__ bq, const float* __restrict__ wkr,
                      float* __restrict__ outb)
{
    __shared__ float part[8][32];
    const int j = blockIdx.x * 32 + threadIdx.x;
    float s = 0.f;
    for (int i = threadIdx.y; i < 1024; i += 8)
        s += bq[i] * wkr[(long long)i * 1024 + j];
    part[threadIdx.y][threadIdx.x] = s;
    __syncthreads();
    if (threadIdx.y == 0) {
        float t = 0.f;
        #pragma unroll
        for (int k = 0; k < 8; k++) t += part[k][threadIdx.x];
        outb[j] = t;
    }
}

// ---------------------------------------------------------------------------
// bvo[n] = bo[n] + sum_i wo[n,i] * bv[i]   (one warp per n)
// ---------------------------------------------------------------------------
__global__ void bvo_k(const float* __restrict__ wo, const float* __restrict__ bv,
                      const float* __restrict__ bo, float* __restrict__ outb)
{
    const int w = threadIdx.x >> 5, l = threadIdx.x & 31;
    const int n = blockIdx.x * 8 + w;
    float s = 0.f;
    for (int i = l; i < 1024; i += 32) s += wo[(long long)n * 1024 + i] * bv[i];
    #pragma unroll
    for (int o = 16; o > 0; o >>= 1) s += __shfl_xor_sync(0xFFFFFFFFu, s, o);
    if (l == 0) outb[n] = s + bo[n];
}

// ---------------------------------------------------------------------------
// LayerNorm over D=1024 (output tf32-rounded)
// ---------------------------------------------------------------------------
__global__ void ln_k(const float* __restrict__ x, const float* __restrict__ g,
                     const float* __restrict__ b, float* __restrict__ y)
{
    const long long row = blockIdx.x;
    const float* xr = x + row * D_MODEL;
    float* yr = y + row * D_MODEL;
    const int t = threadIdx.x;

    float v[4], s = 0.f, s2 = 0.f;
    #pragma unroll
    for (int i = 0; i < 4; i++) {
        v[i] = xr[t + i * 256];
        s  += v[i];
        s2 += v[i] * v[i];
    }
    #pragma unroll
    for (int o = 16; o > 0; o >>= 1) {
        s  += __shfl_xor_sync(0xFFFFFFFFu, s,  o);
        s2 += __shfl_xor_sync(0xFFFFFFFFu, s2, o);
    }
    __shared__ float shs[8], shs2[8];
    if ((t & 31) == 0) { shs[t >> 5] = s; shs2[t >> 5] = s2; }
    __syncthreads();
    float S = 0.f, S2 = 0.f;
    #pragma unroll
    for (int w = 0; w < 8; w++) { S += shs[w]; S2 += shs2[w]; }

    const float mean = S * (1.0f / D_MODEL);
    const float var  = S2 * (1.0f / D_MODEL) - mean * mean;
    const float inv  = rsqrtf(var + 1e-5f);
    #pragma unroll
    for (int i = 0; i < 4; i++) {
        const int c = t + i * 256;
        yr[c] = f2tf_f((v[i] - mean) * inv * g[c] + b[c]);
    }
}

// ---------------------------------------------------------------------------
// Row softmax in-place fp32 (optionally + log(prev_mask + 1e-6)); tf32 out
// ---------------------------------------------------------------------------
__global__ void softmax_k(float* __restrict__ s, const float* __restrict__ pm, int cols)
{
    const long long row = blockIdx.x;
    float* r = s + row * cols;
    const float* pmr = pm ? pm + row * cols : nullptr;
    const int t = threadIdx.x;
    const int nc = cols >> 8;

    float lv[16];
    float mx = -1e30f;
    for (int i = 0; i < nc; i++) {
        float v = r[t + (i << 8)];
        if (pmr) v += logf(pmr[t + (i << 8)] + 1e-6f);
        lv[i] = v;
        mx = fmaxf(mx, v);
    }
    #pragma unroll
    for (int o = 16; o > 0; o >>= 1)
        mx = fmaxf(mx, __shfl_xor_sync(0xFFFFFFFFu, mx, o));
    __shared__ float shm[8], shsum[8];
    if ((t & 31) == 0) shm[t >> 5] = mx;
    __syncthreads();
    float MX = shm[0];
    #pragma unroll
    for (int w = 1; w < 8; w++) MX = fmaxf(MX, shm[w]);

    float sum = 0.f;
    for (int i = 0; i < nc; i++) {
        const float e = expf(lv[i] - MX);
        lv[i] = e;
        sum += e;
    }
    #pragma unroll
    for (int o = 16; o > 0; o >>= 1)
        sum += __shfl_xor_sync(0xFFFFFFFFu, sum, o);
    if ((t & 31) == 0) shsum[t >> 5] = sum;
    __syncthreads();
    float SUM = 0.f;
    #pragma unroll
    for (int w = 0; w < 8; w++) SUM += shsum[w];

    const float inv = 1.0f / SUM;
    for (int i = 0; i < nc; i++) r[t + (i << 8)] = f2tf_f(lv[i] * inv);
}

// ---------------------------------------------------------------------------
// kernel_launch
// ---------------------------------------------------------------------------
extern "C" void kernel_launch(void* const* d_in, const int* in_sizes, int n_in,
                              void* d_out, int out_size)
{
    const float* query    = (const float*)d_in[0];
    const float* memory   = (const float*)d_in[1];
    const float* prevmask = (const float*)d_in[2];
    const float* sa_in_w  = (const float*)d_in[5];
    const float* sa_in_b  = (const float*)d_in[6];
    const float* sa_out_w = (const float*)d_in[7];
    const float* sa_out_b = (const float*)d_in[8];
    const float* ln1_g = (const float*)d_in[9];
    const float* ln1_b = (const float*)d_in[10];
    const float* ln2_g = (const float*)d_in[11];
    const float* ln2_b = (const float*)d_in[12];
    const float* ln3_g = (const float*)d_in[13];
    const float* ln3_b = (const float*)d_in[14];
    const float* wq = (const float*)d_in[15];
    const float* bq = (const float*)d_in[16];
    const float* wk = (const float*)d_in[17];
    // bk eliminated: its score contribution is constant per softmax row.
    const float* wv = (const float*)d_in[19];
    const float* bv = (const float*)d_in[20];
    const float* wo = (const float*)d_in[21];
    const float* bo = (const float*)d_in[22];
    const float* w1 = (const float*)d_in[23];
    const float* b1 = (const float*)d_in[24];
    const float* w2 = (const float*)d_in[25];
    const float* b2 = (const float*)d_in[26];
    const float* mask_w = (const float*)d_in[27];
    const float* mask_b = (const float*)d_in[28];

    float* scr = nullptr;
    cudaGetSymbolAddress((void**)&scr, g_scratch);

    float* gx    = scr + OFF_X;
    float* gq    = scr + OFF_PACK;
    float* gk    = scr + OFF_PACK + 2097152LL;
    float* gv    = scr + OFF_PACK + 4194304LL;
    float* gsc   = scr + OFF_SCORES;
    float* gorep = scr + OFF_OREP;
    float* gq1   = scr + OFF_Q1;
    float* gQp   = scr + OFF_QP;
    float* gq2   = scr + OFF_Q2;
    float* gh    = scr + OFF_H;
    float* gqm   = scr + OFF_QM;
    float* gwkr  = scr + OFF_WKR;
    float* gwqT  = scr + OFF_WQT;
    float* gWqk  = scr + OFF_WQK;
    float* gWvo  = scr + OFF_WVO;
    float* gbqk  = scr + OFF_BQK;
    float* gbvo  = scr + OFF_BVO;

    float* out_q = (float*)d_out;
    float* out_m = out_q + (long long)M_TOK * D_MODEL;

    const float inv_sqrt_hd = 0.088388347648318447f;
    const float inv_sqrt_d  = 0.03125f;

    cudaFuncSetAttribute(gemm_tc<0,0,1,128,1,0,0,0>, cudaFuncAttributeMaxDynamicSharedMemorySize, GS_BYTES(128));
    cudaFuncSetAttribute(gemm_tc<0,0,0,128,0,0,0,0>, cudaFuncAttributeMaxDynamicSharedMemorySize, GS_BYTES(128));
    cudaFuncSetAttribute(gemm_tc<1,0,2,64,1,0,0,0>,  cudaFuncAttributeMaxDynamicSharedMemorySize, GS_BYTES(64));
    cudaFuncSetAttribute(gemm_tc<0,0,0,64,0,0,0,0>,  cudaFuncAttributeMaxDynamicSharedMemorySize, GS_BYTES(64));
    cudaFuncSetAttribute(gemm_tc<1,0,0,64,1,0,0,0>,  cudaFuncAttributeMaxDynamicSharedMemorySize, GS_BYTES(64));
    cudaFuncSetAttribute(gemm_tc<0,0,0,128,0,0,1,1>, cudaFuncAttributeMaxDynamicSharedMemorySize, GS_BYTES(128));
    cudaFuncSetAttribute(gemm_tc<1,0,0,128,1,0,1,0>, cudaFuncAttributeMaxDynamicSharedMemorySize, GS_BYTES(128));
    cudaFuncSetAttribute(gemm_tc<0,1,0,128,1,0,0,0>, cudaFuncAttributeMaxDynamicSharedMemorySize, GS_BYTES(128));
    cudaFuncSetAttribute(gemm_tc<0,0,0,64,0,1,0,0>,  cudaFuncAttributeMaxDynamicSharedMemorySize, GS_BYTES(64));
    cudaFuncSetAttribute(gemm_tc<0,2,0,128,0,0,0,0>, cudaFuncAttributeMaxDynamicSharedMemorySize, GS_BYTES(128));

    // --- weight precomputes ---
    round4_k<<<1024, 256>>>(wk, gwkr, 262144);
    transpose_k<<<dim3(32,32), dim3(32,8)>>>(wq, gwqT);
    gemm_tc<1,0,0,64,1,0,0,0><<<dim3(8,16,1), 128, GS_BYTES(64)>>>(gwqT, gwkr, nullptr, nullptr,
        gWqk, nullptr, 1024, 1024, 1024, 1024, 1024, 0, 0, 0, 1.0f, 0, 0);
    bqk_k<<<32, dim3(32,8)>>>(bq, gwkr, gbqk);
    gemm_tc<1,0,0,64,1,0,0,0><<<dim3(8,16,1), 128, GS_BYTES(64)>>>(wo, wv, nullptr, nullptr,
        gWvo, nullptr, 1024, 1024, 1024, 1024, 1024, 0, 0, 0, 1.0f, 0, 0);
    bvo_k<<<128, 256>>>(wo, bv, bo, gbvo);

    // 1. ln1(query) (rounds)
    ln_k<<<M_TOK, 256>>>(query, ln1_g, ln1_b, gx);

    // 2. QKV projection + head-pack (rounds)
    gemm_tc<0,0,1,128,1,0,0,0><<<dim3(24,16,1), 128, GS_BYTES(128)>>>(gx, sa_in_w, sa_in_b, nullptr,
        gq, nullptr, M_TOK, 3*D_MODEL, D_MODEL, D_MODEL, D_MODEL, 0, 0, 0, 1.0f, 0, 0);

    // 3. self-attn scores (batched 64)
    gemm_tc<0,0,0,128,0,0,0,0><<<dim3(2,2,64), 128, GS_BYTES(128)>>>(gq, gk, nullptr, nullptr,
        gsc, nullptr, NQ, NQ, HDIM, HDIM, HDIM, 256LL*128, 256LL*128, 256LL*256,
        inv_sqrt_hd, 0, 0);

    // 4. softmax (rounds)
    softmax_k<<<64*256, 256>>>(gsc, nullptr, 256);

    // 5. o = attn @ v + o-pack (rounds) -> gorep [2048,1024]
    gemm_tc<1,0,2,64,1,0,0,0><<<dim3(1,4,64), 128, GS_BYTES(64)>>>(gsc, gv, nullptr, nullptr,
        gorep, nullptr, NQ, HDIM, NQ, NQ, HDIM, 256LL*256, 256LL*128, 0, 1.0f, 0, 0);

    // 6. self out-proj + residual (fp32 exact)
    gemm_tc<0,0,0,64,0,0,0,0><<<dim3(8,32,1), 128, GS_BYTES(64)>>>(gorep, sa_out_w, sa_out_b, query,
        gq1, nullptr, M_TOK, D_MODEL, D_MODEL, D_MODEL, D_MODEL, 0, 0, 0, 1.0f, 0, 0);

    // 7. ln2 (rounds)
    ln_k<<<M_TOK, 256>>>(gq1, ln2_g, ln2_b, gx);

    // 8. Q' = ln2 @ Wqk + bqk  -> gQp b-major (rounds)
    gemm_tc<1,0,0,64,1,0,0,0><<<dim3(8,32,1), 128, GS_BYTES(64)>>>(gx, gWqk, gbqk, nullptr,
        gQp, nullptr, M_TOK, D_MODEL, D_MODEL, D_MODEL, D_MODEL, 0, 0, 0, 1.0f, 8, 256);

    // 10. cross scores = Q' @ memory_b^T / sqrt(D)  + log(prev_mask) fused
    gemm_tc<0,0,0,128,0,0,1,1><<<dim3(2,32,8), 128, GS_BYTES(128)>>>(gQp, memory, nullptr, nullptr,
        gsc, (float*)prevmask, NQ, SEQ_S, D_MODEL, D_MODEL, 8192,
        256LL*1024, 1024LL, 256LL*4096, inv_sqrt_d, 0, 0);

    // 11. softmax (mask already added) (rounds)
    softmax_k<<<BATCH*NQ, 256>>>(gsc, nullptr, SEQ_S);

    // 12. AM = attn @ memory_b (rounds), MTILE=128, partner m-tiles adjacent
    gemm_tc<1,0,0,128,1,0,1,0><<<dim3(2,8,8), 128, GS_BYTES(128)>>>(gsc, memory, nullptr, nullptr,
        gorep, nullptr, NQ, D_MODEL, SEQ_S, SEQ_S, 8192,
        256LL*4096, 1024LL, 256LL*1024, 1.0f, 0, 0);

    // 13. out = AM @ Wvo^T + bvo + resid -> [NQ,B,D] (fp32 exact)
    gemm_tc<0,0,0,64,0,0,0,0><<<dim3(8,32,1), 128, GS_BYTES(64)>>>(gorep, gWvo, gbvo, gq1,
        gq2, nullptr, M_TOK, D_MODEL, D_MODEL, D_MODEL, D_MODEL, 0, 0, 0, 1.0f, 256, 8);

    // 14. ln3 (rounds)
    ln_k<<<M_TOK, 256>>>(gq2, ln3_g, ln3_b, gx);

    // 15. FFN1 + GELU (rounds)
    gemm_tc<0,1,0,128,1,0,0,0><<<dim3(32,16,1), 128, GS_BYTES(128)>>>(gx, w1, b1, nullptr,
        gh, nullptr, M_TOK, FF_DIM, D_MODEL, D_MODEL, D_MODEL, 0, 0, 0, 1.0f, 0, 0);

    // 16. FFN2 + residual -> out_q exact; dual rounded gather -> gqm
    gemm_tc<0,0,0,64,0,1,0,0><<<dim3(8,32,1), 128, GS_BYTES(64)>>>(gh, w2, b2, gq2,
        out_q, gqm, M_TOK, D_MODEL, FF_DIM, FF_DIM, FF_DIM, 0, 0, 0, 1.0f, 0, 0);

    // 17. mask logits + sigmoid -> out_m
    gemm_tc<0,2,0,128,0,0,0,0><<<dim3(32,16,1), 128, GS_BYTES(128)>>>(gqm, mask_w, mask_b, nullptr,
        out_m, nullptr, M_TOK, SEQ_S, D_MODEL, D_MODEL, D_MODEL, 0, 0, 0, 1.0f, 0, 0);
}

// round 17
// speedup vs baseline: 2.2217x; 1.0147x over previous
#include <cuda_runtime.h>
#include <math.h>

// ---------------------------------------------------------------------------
// Problem constants
// ---------------------------------------------------------------------------
#define D_MODEL 1024
#define NHEAD   8
#define HDIM    128
#define NQ      256
#define BATCH   8
#define SEQ_S   4096
#define FF_DIM  4096
#define M_TOK   (NQ*BATCH)       // 2048
#define M_MEM   (SEQ_S*BATCH)    // 32768

// ---------------------------------------------------------------------------
// Scratch (offsets in floats)
// ---------------------------------------------------------------------------
#define OFF_X      0LL                       // ln out [2048,1024]
#define OFF_PACK   2097152LL                 // q,k,v packed [3][64][256][128]
#define OFF_SCORES 8388608LL                 // scores (max 8*256*4096)
#define OFF_OREP   16777216LL                // repacked attn-out / AM [2048,1024]
#define OFF_Q1     18874368LL
#define OFF_QP     20971520LL                // Q' (b-major) [2048,1024]
#define OFF_Q2     23068672LL
#define OFF_H      25165824LL                // FFN hidden [2048,4096]
#define OFF_QM     33554432LL                // query gathered [B,NQ,D]
#define OFF_WKR    35651584LL                // rounded wk [1024,1024]
#define OFF_WQT    36700160LL                // wq^T rounded
#define OFF_WQK    37748736LL                // Wqk = wq^T @ wk
#define OFF_WVO    38797312LL                // Wvo = wo @ wv
#define OFF_BQK    39845888LL                // bqk [1024]
#define OFF_BVO    39846912LL                // bvo [1024]
#define OFF_BQKP   39847936LL                // bqk partials [8][1024]
#define SCRATCH_TOTAL 39856128LL

__device__ float g_scratch[SCRATCH_TOTAL];

// ---------------------------------------------------------------------------
// Helpers
// ---------------------------------------------------------------------------
__device__ __forceinline__ float gelu_exact(float x) {
    return 0.5f * x * (1.0f + erff(x * 0.70710678118654752f));
}
__device__ __forceinline__ float f2tf_f(float x) {
    unsigned u;
    asm("cvt.rna.tf32.f32 %0, %1;" : "=r"(u) : "f"(x));
    return __uint_as_float(u);
}

// ---------------------------------------------------------------------------
// tf32 tensor-core batched GEMM, 4-stage cp.async pipeline.
// 128 threads, 4 warps. CTA tile MTILE x 128 x 16.
//   C = act( alpha * A @ op(B) + bias + resid )
//   BLAYOUT 0: B is [N,K] (A@B^T). BLAYOUT 1: B is [K,N].
//   ACT: 0 none, 1 gelu, 2 sigmoid.
//   PK: 0 normal (permP/permQ remap; DUAL -> extra rounded gather to C2)
//       1 QKV head-pack epilogue    2 self-AV o-pack epilogue
//   RNDC: round C store to tf32 (rna).
//   SWAP: blockIdx.x -> m-tile (partner m-tiles adjacent in dispatch order).
//   ADDLM: add logf(C2[base+gn] + 1e-6) to scores (cross-attn mask fusion).
// Dynamic smem: GSTAGES * (MTILE*20 + 2560) floats.
// ---------------------------------------------------------------------------
#define GSTAGES 4
#define GS_BYTES(MT_) (GSTAGES * ((MT_)*20 + 2560) * 4)

template<int BLAYOUT, int ACT, int PK, int MTILE, int RNDC, int DUAL, int SWAP, int ADDLM>
__global__ void __launch_bounds__(128, 2)
gemm_tc(const float* __restrict__ A, const float* __restrict__ B,
        const float* __restrict__ bias, const float* __restrict__ resid,
        float* __restrict__ C, float* __restrict__ C2,
        int M, int N, int K, int lda, int ldb,
        long long bA, long long bB, long long bC,
        float alpha, int permP, int permQ)
{
    constexpr int MT   = MTILE / 32;
    constexpr int ASTR = MTILE * 20;
    extern __shared__ float smemf[];
    float* As = smemf;
    float* Bs = smemf + GSTAGES * ASTR;

    const int z  = blockIdx.z;
    const float* Ab = A + (long long)z * bA;
    const float* Bb = B + (long long)z * bB;
    const int m0 = (SWAP ? blockIdx.x : blockIdx.y) * MTILE;
    const int n0 = (SWAP ? blockIdx.y : blockIdx.x) * 128;

    const int tid  = threadIdx.x;
    const int lane = tid & 31;
    const int warp = tid >> 5;
    const int warpM = warp >> 1;
    const int warpN = warp & 1;
    const int lr = lane >> 2;
    const int lc = lane & 3;

    const int a_r0 = tid >> 2;
    const int a_kq = (tid & 3) * 4;
    const float* Aptr = Ab + (long long)(m0 + a_r0) * lda + a_kq;

    const float* Bptr;
    int b1_k0 = 0, b1_nq = 0;
    if (BLAYOUT == 0) {
        Bptr = Bb + (long long)(n0 + a_r0) * ldb + a_kq;
    } else {
        b1_k0 = tid >> 5;
        b1_nq = (tid & 31) * 4;
        Bptr = Bb + (long long)b1_k0 * ldb + n0 + b1_nq;
    }

    const unsigned sAu = (unsigned)__cvta_generic_to_shared(As);
    const unsigned sBu = (unsigned)__cvta_generic_to_shared(Bs);
    const unsigned dA0 = sAu + (unsigned)(a_r0 * 20 + a_kq) * 4u;
    const unsigned dB0 = (BLAYOUT == 0)
        ? sBu + (unsigned)(a_r0 * 20 + a_kq) * 4u
        : sBu + (unsigned)(b1_k0 * 136 + b1_nq) * 4u;

    const int nkt = K >> 4;

    auto issue = [&](int kt, int slot) {
        const long long ka = (long long)kt * 16;
        const unsigned soA = (unsigned)slot * (unsigned)ASTR * 4u;
        const unsigned soB = (unsigned)slot * 2560u * 4u;
        #pragma unroll
        for (int i = 0; i < MT; i++) {
            const float* g = Aptr + (long long)i * 32 * lda + ka;
            unsigned d = dA0 + soA + (unsigned)(i * 32 * 20) * 4u;
            asm volatile("cp.async.cg.shared.global [%0], [%1], 16;\n" :: "r"(d), "l"(g));
        }
        if (BLAYOUT == 0) {
            #pragma unroll
            for (int i = 0; i < 4; i++) {
                const float* g = Bptr + (long long)i * 32 * ldb + ka;
                unsigned d = dB0 + soB + (unsigned)(i * 32 * 20) * 4u;
                asm volatile("cp.async.cg.shared.global [%0], [%1], 16;\n" :: "r"(d), "l"(g));
            }
        } else {
            #pragma unroll
            for (int i = 0; i < 4; i++) {
                const float* g = Bptr + (ka + (long long)i * 4) * ldb;
                unsigned d = dB0 + soB + (unsigned)(i * 4 * 136) * 4u;
                asm volatile("cp.async.cg.shared.global [%0], [%1], 16;\n" :: "r"(d), "l"(g));
            }
        }
        asm volatile("cp.async.commit_group;\n");
    };

    float acc[MT][8][4];
    #pragma unroll
    for (int a = 0; a < MT; a++)
        #pragma unroll
        for (int b = 0; b < 8; b++)
            #pragma unroll
            for (int c = 0; c < 4; c++) acc[a][b][c] = 0.f;

    #pragma unroll
    for (int s = 0; s < GSTAGES - 1; s++) {
        if (s < nkt) issue(s, s);
        else asm volatile("cp.async.commit_group;\n");
    }

    for (int kt = 0; kt < nkt; kt++) {
        asm volatile("cp.async.wait_group %0;\n" :: "n"(GSTAGES - 2));
        __syncthreads();

        const int nx = kt + GSTAGES - 1;
        if (nx < nkt) issue(nx, nx & (GSTAGES - 1));
        else asm volatile("cp.async.commit_group;\n");

        const float* Asb = As + (kt & (GSTAGES - 1)) * ASTR;
        const float* Bsb = Bs + (kt & (GSTAGES - 1)) * 2560;

        #pragma unroll
        for (int k8 = 0; k8 < 2; k8++) {
            const int c = k8 * 8 + lc;
            unsigned bf[8][2];
            #pragma unroll
            for (int nt = 0; nt < 8; nt++) {
                if (BLAYOUT == 0) {
                    const int nn = warpN*64 + nt*8 + lr;
                    bf[nt][0] = __float_as_uint(Bsb[nn*20 + c]);
                    bf[nt][1] = __float_as_uint(Bsb[nn*20 + c + 4]);
                } else {
                    const int kk = k8*8 + lc;
                    const int nn = warpN*64 + nt*8 + lr;
                    bf[nt][0] = __float_as_uint(Bsb[kk*136 + nn]);
                    bf[nt][1] = __float_as_uint(Bsb[(kk+4)*136 + nn]);
                }
            }
            #pragma unroll
            for (int mt = 0; mt < MT; mt++) {
                const int r = warpM*(MTILE/2) + mt*16 + lr;
                unsigned a0 = __float_as_uint(Asb[r*20 + c]);
                unsigned a1 = __float_as_uint(Asb[(r+8)*20 + c]);
                unsigned a2 = __float_as_uint(Asb[r*20 + c + 4]);
                unsigned a3 = __float_as_uint(Asb[(r+8)*20 + c + 4]);
                #pragma unroll
                for (int nt = 0; nt < 8; nt++) {
                    asm volatile(
                        "mma.sync.aligned.m16n8k8.row.col.f32.tf32.tf32.f32 "
                        "{%0,%1,%2,%3}, {%4,%5,%6,%7}, {%8,%9}, {%0,%1,%2,%3};"
                        : "+f"(acc[mt][nt][0]), "+f"(acc[mt][nt][1]),
                          "+f"(acc[mt][nt][2]), "+f"(acc[mt][nt][3])
                        : "r"(a0), "r"(a1), "r"(a2), "r"(a3),
                          "r"(bf[nt][0]), "r"(bf[nt][1]));
                }
            }
        }
    }

    // ---- epilogue ----
    #pragma unroll
    for (int mt = 0; mt < MT; mt++) {
        #pragma unroll
        for (int h = 0; h < 2; h++) {
            const int gm = m0 + warpM*(MTILE/2) + mt*16 + lr + h*8;
            #pragma unroll
            for (int nt = 0; nt < 8; nt++) {
                const int gn = n0 + warpN*64 + nt*8 + 2*lc;
                float v0 = acc[mt][nt][2*h+0] * alpha;
                float v1 = acc[mt][nt][2*h+1] * alpha;
                if (PK != 2) {
                    if (bias) { v0 += bias[gn]; v1 += bias[gn+1]; }
                }
                if (PK == 1) {
                    const int b = gm & 7, l = gm >> 3;
                    const int sec = gn >> 10, hh = (gn >> 7) & 7, d = gn & 127;
                    const long long idx = (long long)sec * 2097152LL
                        + ((long long)(b*8 + hh) * 256 + l) * 128 + d;
                    if (RNDC) { v0 = f2tf_f(v0); v1 = f2tf_f(v1); }
                    float2 o; o.x = v0; o.y = v1;
                    *(float2*)(&C[idx]) = o;
                } else if (PK == 2) {
                    const int b = z >> 3, hh = z & 7;
                    const long long idx = ((long long)(gm*8 + b)) * 1024 + hh*128 + gn;
                    if (RNDC) { v0 = f2tf_f(v0); v1 = f2tf_f(v1); }
                    float2 o; o.x = v0; o.y = v1;
                    *(float2*)(&C[idx]) = o;
                } else {
                    const int rm = (permP > 0) ? ((gm % permP) * permQ + gm / permP) : gm;
                    const long long base = (long long)z * bC + (long long)rm * N;
                    if (ADDLM) {
                        v0 += logf(C2[base + gn] + 1e-6f);
                        v1 += logf(C2[base + gn + 1] + 1e-6f);
                    }
                    if (resid) { v0 += resid[base + gn]; v1 += resid[base + gn + 1]; }
                    if (ACT == 1) { v0 = gelu_exact(v0); v1 = gelu_exact(v1); }
                    else if (ACT == 2) {
                        v0 = 1.0f / (1.0f + expf(-v0));
                        v1 = 1.0f / (1.0f + expf(-v1));
                    }
                    float2 o;
                    if (RNDC) { o.x = f2tf_f(v0); o.y = f2tf_f(v1); }
                    else      { o.x = v0; o.y = v1; }
                    *(float2*)(&C[base + gn]) = o;
                    if (DUAL) {
                        const int r2 = (gm & 7) * 256 + (gm >> 3);
                        float2 o2; o2.x = f2tf_f(v0); o2.y = f2tf_f(v1);
                        *(float2*)(&C2[(long long)r2 * N + gn]) = o2;
                    }
                }
            }
        }
    }
}

// ---------------------------------------------------------------------------
// tf32 rounding pass (float4)
// ---------------------------------------------------------------------------
__global__ void round4_k(const float* __restrict__ in, float* __restrict__ out, int n4)
{
    const int i = blockIdx.x * 256 + threadIdx.x;
    if (i < n4) {
        float4 v = ((const float4*)in)[i];
        v.x = f2tf_f(v.x); v.y = f2tf_f(v.y);
        v.z = f2tf_f(v.z); v.w = f2tf_f(v.w);
        ((float4*)out)[i] = v;
    }
}

// ---------------------------------------------------------------------------
// 1024x1024 transpose (rounds output)
// ---------------------------------------------------------------------------
__global__ void transpose_k(const float* __restrict__ in, float* __restrict__ out)
{
    __shared__ float t[32][33];
    const int bx = blockIdx.x * 32, by = blockIdx.y * 32;
    #pragma unroll
    for (int i = 0; i < 32; i += 8)
        t[threadIdx.y + i][threadIdx.x] =
            in[(long long)(by + threadIdx.y + i) * 1024 + bx + threadIdx.x];
    __syncthreads();
    #pragma unroll
    for (int i = 0; i < 32; i += 8)
        out[(long long)(bx + threadIdx.y + i) * 1024 + by + threadIdx.x] =
            f2tf_f(t[threadIdx.x][threadIdx.y + i]);
}

// ---------------------------------------------------------------------------
// bqk stage 1: partial[iy][j] = sum over i in slab iy of bq[i]*wkr[i,j]
// grid (32, 8), block (32, 8): x = j (coalesced), y = i within slab
// ---------------------------------------------------------------------------
__global__ void bqk_part_k(const float* __restrict__ bq, const float* __restrict__ wkr,
                           float* __restrict__ part)
{
    __shared__ float ps[8][32];
    const int j = blockIdx.x * 32 + threadIdx.x;
    const int i0 = blockIdx.y * 128;
    float s = 0.f;
    for (int i = i0 + threadIdx.y; i < i0 + 128; i += 8)
        s += bq[i] * wkr[(long long)i * 1024 + j];
    ps[threadIdx.y][threadIdx.x] = s;
    __syncthreads();
    if (threadIdx.y == 0) {
        float t = 0.f;
        #pragma unroll
        for (int k = 0; k < 8; k++) t += ps[k][threadIdx.x];
        part[(long long)blockIdx.y * 1024 + j] = t;
    }
}

// bqk stage 2: reduce 8 partials per column
__global__ void bqk_red_k(const float* __restrict__ part, float* __restrict__ outb)
{
    const int j = blockIdx.x * 256 + threadIdx.x;
    float s = 0.f;
    #pragma unroll
    for (int k = 0; k < 8; k++) s += part[(long long)k * 1024 + j];
    outb[j] = s;
}

// ---------------------------------------------------------------------------
// bvo[n] = bo[n] + sum_i wo[n,i] * bv[i]   (one warp per n)
// ---------------------------------------------------------------------------
__global__ void bvo_k(const float* __restrict__ wo, const float* __restrict__ bv,
                      const float* __restrict__ bo, float* __restrict__ outb)
{
    const int w = threadIdx.x >> 5, l = threadIdx.x & 31;
    const int n = blockIdx.x * 8 + w;
    float s = 0.f;
    for (int i = l; i < 1024; i += 32) s += wo[(long long)n * 1024 + i] * bv[i];
    #pragma unroll
    for (int o = 16; o > 0; o >>= 1) s += __shfl_xor_sync(0xFFFFFFFFu, s, o);
    if (l == 0) outb[n] = s + bo[n];
}

// ---------------------------------------------------------------------------
// LayerNorm over D=1024 (output tf32-rounded)
// ---------------------------------------------------------------------------
__global__ void ln_k(const float* __restrict__ x, const float* __restrict__ g,
                     const float* __restrict__ b, float* __restrict__ y)
{
    const long long row = blockIdx.x;
    const float* xr = x + row * D_MODEL;
    float* yr = y + row * D_MODEL;
    const int t = threadIdx.x;

    float v[4], s = 0.f, s2 = 0.f;
    #pragma unroll
    for (int i = 0; i < 4; i++) {
        v[i] = xr[t + i * 256];
        s  += v[i];
        s2 += v[i] * v[i];
    }
    #pragma unroll
    for (int o = 16; o > 0; o >>= 1) {
        s  += __shfl_xor_sync(0xFFFFFFFFu, s,  o);
        s2 += __shfl_xor_sync(0xFFFFFFFFu, s2, o);
    }
    __shared__ float shs[8], shs2[8];
    if ((t & 31) == 0) { shs[t >> 5] = s; shs2[t >> 5] = s2; }
    __syncthreads();
    float S = 0.f, S2 = 0.f;
    #pragma unroll
    for (int w = 0; w < 8; w++) { S += shs[w]; S2 += shs2[w]; }

    const float mean = S * (1.0f / D_MODEL);
    const float var  = S2 * (1.0f / D_MODEL) - mean * mean;
    const float inv  = rsqrtf(var + 1e-5f);
    #pragma unroll
    for (int i = 0; i < 4; i++) {
        const int c = t + i * 256;
        yr[c] = f2tf_f((v[i] - mean) * inv * g[c] + b[c]);
    }
}

// ---------------------------------------------------------------------------
// Row softmax in-place fp32 (optionally + log(prev_mask + 1e-6)); tf32 out
// ---------------------------------------------------------------------------
__global__ void softmax_k(float* __restrict__ s, const float* __restrict__ pm, int cols)
{
    const long long row = blockIdx.x;
    float* r = s + row * cols;
    const float* pmr = pm ? pm + row * cols : nullptr;
    const int t = threadIdx.x;
    const int nc = cols >> 8;

    float lv[16];
    float mx = -1e30f;
    for (int i = 0; i < nc; i++) {
        float v = r[t + (i << 8)];
        if (pmr) v += logf(pmr[t + (i << 8)] + 1e-6f);
        lv[i] = v;
        mx = fmaxf(mx, v);
    }
    #pragma unroll
    for (int o = 16; o > 0; o >>= 1)
        mx = fmaxf(mx, __shfl_xor_sync(0xFFFFFFFFu, mx, o));
    __shared__ float shm[8], shsum[8];
    if ((t & 31) == 0) shm[t >> 5] = mx;
    __syncthreads();
    float MX = shm[0];
    #pragma unroll
    for (int w = 1; w < 8; w++) MX = fmaxf(MX, shm[w]);

    float sum = 0.f;
    for (int i = 0; i < nc; i++) {
        const float e = expf(lv[i] - MX);
        lv[i] = e;
        sum += e;
    }
    #pragma unroll
    for (int o = 16; o > 0; o >>= 1)
        sum += __shfl_xor_sync(0xFFFFFFFFu, sum, o);
    if ((t & 31) == 0) shsum[t >> 5] = sum;
    __syncthreads();
    float SUM = 0.f;
    #pragma unroll
    for (int w = 0; w < 8; w++) SUM += shsum[w];

    const float inv = 1.0f / SUM;
    for (int i = 0; i < nc; i++) r[t + (i << 8)] = f2tf_f(lv[i] * inv);
}

// ---------------------------------------------------------------------------
// kernel_launch
// ---------------------------------------------------------------------------
extern "C" void kernel_launch(void* const* d_in, const int* in_sizes, int n_in,
                              void* d_out, int out_size)
{
    const float* query    = (const float*)d_in[0];
    const float* memory   = (const float*)d_in[1];
    const float* prevmask = (const float*)d_in[2];
    const float* sa_in_w  = (const float*)d_in[5];
    const float* sa_in_b  = (const float*)d_in[6];
    const float* sa_out_w = (const float*)d_in[7];
    const float* sa_out_b = (const float*)d_in[8];
    const float* ln1_g = (const float*)d_in[9];
    const float* ln1_b = (const float*)d_in[10];
    const float* ln2_g = (const float*)d_in[11];
    const float* ln2_b = (const float*)d_in[12];
    const float* ln3_g = (const float*)d_in[13];
    const float* ln3_b = (const float*)d_in[14];
    const float* wq = (const float*)d_in[15];
    const float* bq = (const float*)d_in[16];
    const float* wk = (const float*)d_in[17];
    // bk eliminated: its score contribution is constant per softmax row.
    const float* wv = (const float*)d_in[19];
    const float* bv = (const float*)d_in[20];
    const float* wo = (const float*)d_in[21];
    const float* bo = (const float*)d_in[22];
    const float* w1 = (const float*)d_in[23];
    const float* b1 = (const float*)d_in[24];
    const float* w2 = (const float*)d_in[25];
    const float* b2 = (const float*)d_in[26];
    const float* mask_w = (const float*)d_in[27];
    const float* mask_b = (const float*)d_in[28];

    float* scr = nullptr;
    cudaGetSymbolAddress((void**)&scr, g_scratch);

    float* gx    = scr + OFF_X;
    float* gq    = scr + OFF_PACK;
    float* gk    = scr + OFF_PACK + 2097152LL;
    float* gv    = scr + OFF_PACK + 4194304LL;
    float* gsc   = scr + OFF_SCORES;
    float* gorep = scr + OFF_OREP;
    float* gq1   = scr + OFF_Q1;
    float* gQp   = scr + OFF_QP;
    float* gq2   = scr + OFF_Q2;
    float* gh    = scr + OFF_H;
    float* gqm   = scr + OFF_QM;
    float* gwkr  = scr + OFF_WKR;
    float* gwqT  = scr + OFF_WQT;
    float* gWqk  = scr + OFF_WQK;
    float* gWvo  = scr + OFF_WVO;
    float* gbqk  = scr + OFF_BQK;
    float* gbvo  = scr + OFF_BVO;
    float* gbqkp = scr + OFF_BQKP;

    float* out_q = (float*)d_out;
    float* out_m = out_q + (long long)M_TOK * D_MODEL;

    const float inv_sqrt_hd = 0.088388347648318447f;
    const float inv_sqrt_d  = 0.03125f;

    cudaFuncSetAttribute(gemm_tc<0,0,1,128,1,0,0,0>, cudaFuncAttributeMaxDynamicSharedMemorySize, GS_BYTES(128));
    cudaFuncSetAttribute(gemm_tc<0,0,0,128,0,0,0,0>, cudaFuncAttributeMaxDynamicSharedMemorySize, GS_BYTES(128));
    cudaFuncSetAttribute(gemm_tc<1,0,2,64,1,0,0,0>,  cudaFuncAttributeMaxDynamicSharedMemorySize, GS_BYTES(64));
    cudaFuncSetAttribute(gemm_tc<0,0,0,64,0,0,0,0>,  cudaFuncAttributeMaxDynamicSharedMemorySize, GS_BYTES(64));
    cudaFuncSetAttribute(gemm_tc<1,0,0,64,1,0,0,0>,  cudaFuncAttributeMaxDynamicSharedMemorySize, GS_BYTES(64));
    cudaFuncSetAttribute(gemm_tc<0,0,0,128,0,0,1,1>, cudaFuncAttributeMaxDynamicSharedMemorySize, GS_BYTES(128));
    cudaFuncSetAttribute(gemm_tc<1,0,0,64,1,0,1,0>,  cudaFuncAttributeMaxDynamicSharedMemorySize, GS_BYTES(64));
    cudaFuncSetAttribute(gemm_tc<0,1,0,128,1,0,0,0>, cudaFuncAttributeMaxDynamicSharedMemorySize, GS_BYTES(128));
    cudaFuncSetAttribute(gemm_tc<0,0,0,64,0,1,0,0>,  cudaFuncAttributeMaxDynamicSharedMemorySize, GS_BYTES(64));
    cudaFuncSetAttribute(gemm_tc<0,2,0,128,0,0,0,0>, cudaFuncAttributeMaxDynamicSharedMemorySize, GS_BYTES(128));

    // --- weight precomputes ---
    round4_k<<<1024, 256>>>(wk, gwkr, 262144);
    transpose_k<<<dim3(32,32), dim3(32,8)>>>(wq, gwqT);
    gemm_tc<1,0,0,64,1,0,0,0><<<dim3(8,16,1), 128, GS_BYTES(64)>>>(gwqT, gwkr, nullptr, nullptr,
        gWqk, nullptr, 1024, 1024, 1024, 1024, 1024, 0, 0, 0, 1.0f, 0, 0);
    bqk_part_k<<<dim3(32,8), dim3(32,8)>>>(bq, gwkr, gbqkp);
    bqk_red_k<<<4, 256>>>(gbqkp, gbqk);
    gemm_tc<1,0,0,64,1,0,0,0><<<dim3(8,16,1), 128, GS_BYTES(64)>>>(wo, wv, nullptr, nullptr,
        gWvo, nullptr, 1024, 1024, 1024, 1024, 1024, 0, 0, 0, 1.0f, 0, 0);
    bvo_k<<<128, 256>>>(wo, bv, bo, gbvo);

    // 1. ln1(query) (rounds)
    ln_k<<<M_TOK, 256>>>(query, ln1_g, ln1_b, gx);

    // 2. QKV projection + head-pack (rounds)
    gemm_tc<0,0,1,128,1,0,0,0><<<dim3(24,16,1), 128, GS_BYTES(128)>>>(gx, sa_in_w, sa_in_b, nullptr,
        gq, nullptr, M_TOK, 3*D_MODEL, D_MODEL, D_MODEL, D_MODEL, 0, 0, 0, 1.0f, 0, 0);

    // 3. self-attn scores (batched 64)
    gemm_tc<0,0,0,128,0,0,0,0><<<dim3(2,2,64), 128, GS_BYTES(128)>>>(gq, gk, nullptr, nullptr,
        gsc, nullptr, NQ, NQ, HDIM, HDIM, HDIM, 256LL*128, 256LL*128, 256LL*256,
        inv_sqrt_hd, 0, 0);

    // 4. softmax (rounds)
    softmax_k<<<64*256, 256>>>(gsc, nullptr, 256);

    // 5. o = attn @ v + o-pack (rounds) -> gorep [2048,1024]
    gemm_tc<1,0,2,64,1,0,0,0><<<dim3(1,4,64), 128, GS_BYTES(64)>>>(gsc, gv, nullptr, nullptr,
        gorep, nullptr, NQ, HDIM, NQ, NQ, HDIM, 256LL*256, 256LL*128, 0, 1.0f, 0, 0);

    // 6. self out-proj + residual (fp32 exact)
    gemm_tc<0,0,0,64,0,0,0,0><<<dim3(8,32,1), 128, GS_BYTES(64)>>>(gorep, sa_out_w, sa_out_b, query,
        gq1, nullptr, M_TOK, D_MODEL, D_MODEL, D_MODEL, D_MODEL, 0, 0, 0, 1.0f, 0, 0);

    // 7. ln2 (rounds)
    ln_k<<<M_TOK, 256>>>(gq1, ln2_g, ln2_b, gx);

    // 8. Q' = ln2 @ Wqk + bqk  -> gQp b-major (rounds)
    gemm_tc<1,0,0,64,1,0,0,0><<<dim3(8,32,1), 128, GS_BYTES(64)>>>(gx, gWqk, gbqk, nullptr,
        gQp, nullptr, M_TOK, D_MODEL, D_MODEL, D_MODEL, D_MODEL, 0, 0, 0, 1.0f, 8, 256);

    // 10. cross scores = Q' @ memory_b^T / sqrt(D)  + log(prev_mask) fused
    gemm_tc<0,0,0,128,0,0,1,1><<<dim3(2,32,8), 128, GS_BYTES(128)>>>(gQp, memory, nullptr, nullptr,
        gsc, (float*)prevmask, NQ, SEQ_S, D_MODEL, D_MODEL, 8192,
        256LL*1024, 1024LL, 256LL*4096, inv_sqrt_d, 0, 0);

    // 11. softmax (mask already added) (rounds)
    softmax_k<<<BATCH*NQ, 256>>>(gsc, nullptr, SEQ_S);

    // 12. AM = attn @ memory_b (rounds), MTILE=64 -> 256 CTAs (86% fill),
    //     SWAP keeps the 4 partner m-tiles adjacent for L2 dedup of B stripes
    gemm_tc<1,0,0,64,1,0,1,0><<<dim3(4,8,8), 128, GS_BYTES(64)>>>(gsc, memory, nullptr, nullptr,
        gorep, nullptr, NQ, D_MODEL, SEQ_S, SEQ_S, 8192,
        256LL*4096, 1024LL, 256LL*1024, 1.0f, 0, 0);

    // 13. out = AM @ Wvo^T + bvo + resid -> [NQ,B,D] (fp32 exact)
    gemm_tc<0,0,0,64,0,0,0,0><<<dim3(8,32,1), 128, GS_BYTES(64)>>>(gorep, gWvo, gbvo, gq1,
        gq2, nullptr, M_TOK, D_MODEL, D_MODEL, D_MODEL, D_MODEL, 0, 0, 0, 1.0f, 256, 8);

    // 14. ln3 (rounds)
    ln_k<<<M_TOK, 256>>>(gq2, ln3_g, ln3_b, gx);

    // 15. FFN1 + GELU (rounds)
    gemm_tc<0,1,0,128,1,0,0,0><<<dim3(32,16,1), 128, GS_BYTES(128)>>>(gx, w1, b1, nullptr,
        gh, nullptr, M_TOK, FF_DIM, D_MODEL, D_MODEL, D_MODEL, 0, 0, 0, 1.0f, 0, 0);

    // 16. FFN2 + residual -> out_q exact; dual rounded gather -> gqm
    gemm_tc<0,0,0,64,0,1,0,0><<<dim3(8,32,1), 128, GS_BYTES(64)>>>(gh, w2, b2, gq2,
        out_q, gqm, M_TOK, D_MODEL, FF_DIM, FF_DIM, FF_DIM, 0, 0, 0, 1.0f, 0, 0);

    // 17. mask logits + sigmoid -> out_m
    gemm_tc<0,2,0,128,0,0,0,0><<<dim3(32,16,1), 128, GS_BYTES(128)>>>(gqm, mask_w, mask_b, nullptr,
        out_m, nullptr, M_TOK, SEQ_S, D_MODEL, D_MODEL, D_MODEL, 0, 0, 0, 1.0f, 0, 0);
}